// round 15
// baseline (speedup 1.0000x reference)
#include <cuda_runtime.h>
#include <cuda_fp16.h>
#include <math.h>
#include <stdint.h>

#define NSEQ 64
#define TT   256
#define FF   64
#define DMM  128
#define DII  256
#define DSS  16
#define DTRR 8
#define ROWS (NSEQ*TT)
#define LNEPS 1e-5f
#define CHK  16
#define NBUF 4
#define NC   (TT/CHK)
#define CXT  32          // convxproj time-tile

// ---------------- scratch ----------------
__device__ float   g_h    [ROWS*DMM];
__device__ __half  g_xih  [ROWS*DII];
__device__ __half2 g_szh  [ROWS*DII/2];
__device__ float   g_xdbl [ROWS*40];
__device__ float2  g_coefA[ROWS*DII];
__device__ __half2 g_coefB[ROWS*DII];
__device__ __half  g_ymh  [ROWS*DII];
__device__ __half  g_opwh [2*DMM*DII];
__device__ __half  g_xpwh [2*40*DII];
__device__ float   g_part [NSEQ*4*DMM];

// ---------------- helpers ----------------
__device__ __forceinline__ uint32_t smem_u32(const void* p) {
    return (uint32_t)__cvta_generic_to_shared(p);
}
__device__ __forceinline__ void mma_tf32(float* c, const uint32_t* a, const uint32_t* b) {
    asm volatile(
        "mma.sync.aligned.m16n8k8.row.col.f32.tf32.tf32.f32 "
        "{%0,%1,%2,%3}, {%4,%5,%6,%7}, {%8,%9}, {%0,%1,%2,%3};"
        : "+f"(c[0]), "+f"(c[1]), "+f"(c[2]), "+f"(c[3])
        : "r"(a[0]), "r"(a[1]), "r"(a[2]), "r"(a[3]), "r"(b[0]), "r"(b[1]));
}
__device__ __forceinline__ void mma_f16(float* c, const uint32_t* a, const uint32_t* b) {
    asm volatile(
        "mma.sync.aligned.m16n8k16.row.col.f32.f16.f16.f32 "
        "{%0,%1,%2,%3}, {%4,%5,%6,%7}, {%8,%9}, {%0,%1,%2,%3};"
        : "+f"(c[0]), "+f"(c[1]), "+f"(c[2]), "+f"(c[3])
        : "r"(a[0]), "r"(a[1]), "r"(a[2]), "r"(a[3]), "r"(b[0]), "r"(b[1]));
}
__device__ __forceinline__ void row_stats128(float v, float& mu, float& var) {
    float s = v, q = v * v;
    #pragma unroll
    for (int o = 16; o; o >>= 1) {
        s += __shfl_down_sync(0xffffffffu, s, o);
        q += __shfl_down_sync(0xffffffffu, q, o);
    }
    __shared__ float ss[4], sq[4];
    int w = threadIdx.x >> 5;
    if ((threadIdx.x & 31) == 0) { ss[w] = s; sq[w] = q; }
    __syncthreads();
    s = ss[0] + ss[1] + ss[2] + ss[3];
    q = sq[0] + sq[1] + sq[2] + sq[3];
    __syncthreads();
    mu  = s * (1.0f / DMM);
    var = q * (1.0f / DMM) - mu * mu;
}
__device__ __forceinline__ void epowers(float p, float* e) {
    e[0] = p;
    e[1] = p * p;
    e[2] = e[1] * p;     e[3]  = e[1] * e[1];
    e[4] = e[3] * p;     e[5]  = e[3] * e[1];
    e[6] = e[3] * e[2];  e[7]  = e[3] * e[3];
    e[8] = e[7] * p;     e[9]  = e[7] * e[1];
    e[10] = e[7] * e[2]; e[11] = e[7] * e[3];
    e[12] = e[7] * e[4]; e[13] = e[7] * e[5];
    e[14] = e[7] * e[6]; e[15] = e[7] * e[7];
}

// ---------------- weight conversion ----------------
__global__ void __launch_bounds__(256) cvt_weights_kernel(
    const float* __restrict__ opw, const float* __restrict__ xpw)
{
    int idx = blockIdx.x * 256 + threadIdx.x;
    const int n_op = 2 * DMM * DII / 2;
    const int n_xp = 2 * 40 * DII / 2;
    if (idx < n_op) {
        float2 v = *(const float2*)(opw + idx * 2);
        ((__half2*)g_opwh)[idx] = __floats2half2_rn(v.x, v.y);
    } else if (idx < n_op + n_xp) {
        int j = idx - n_op;
        float2 v = *(const float2*)(xpw + j * 2);
        ((__half2*)g_xpwh)[j] = __floats2half2_rn(v.x, v.y);
    }
}

// ---------------- tensorized input projection ----------------
__global__ void __launch_bounds__(256) input_proj_mma(
    const float* __restrict__ x, const float* __restrict__ w, const float* __restrict__ bias)
{
    extern __shared__ float sm[];
    float* As = sm;
    float* Bs = sm + 64 * 68;
    int n = blockIdx.x, t0 = blockIdx.y * 64;
    int tid = threadIdx.x;

    #pragma unroll
    for (int p = 0; p < 4; p++) {
        int f = p * 16 + (tid >> 4), t4 = (tid & 15) * 4;
        float4 v = *(const float4*)(x + ((size_t)(n * FF + f)) * TT + t0 + t4);
        As[(t4 + 0) * 68 + f] = v.x;
        As[(t4 + 1) * 68 + f] = v.y;
        As[(t4 + 2) * 68 + f] = v.z;
        As[(t4 + 3) * 68 + f] = v.w;
    }
    #pragma unroll
    for (int i = 0; i < 8; i++) {
        int idx = tid + i * 256;
        int row = idx >> 4, c4 = (idx & 15) << 2;
        *(float4*)&Bs[row * 68 + c4] = *(const float4*)(w + row * 64 + c4);
    }
    __syncthreads();

    int warp = tid >> 5, lane = tid & 31;
    int gid = lane >> 2, tig = lane & 3;
    int m0 = (warp & 1) * 32, n0 = (warp >> 1) * 32;

    float acc[2][4][4];
    #pragma unroll
    for (int i = 0; i < 2; i++)
        #pragma unroll
        for (int j = 0; j < 4; j++)
            #pragma unroll
            for (int k = 0; k < 4; k++) acc[i][j][k] = 0.f;

    #pragma unroll
    for (int kb = 0; kb < 64; kb += 8) {
        uint32_t afr[2][4], bfr[4][2];
        #pragma unroll
        for (int mt = 0; mt < 2; mt++) {
            int r = m0 + mt * 16 + gid;
            afr[mt][0] = __float_as_uint(As[r * 68 + kb + tig]);
            afr[mt][1] = __float_as_uint(As[(r + 8) * 68 + kb + tig]);
            afr[mt][2] = __float_as_uint(As[r * 68 + kb + tig + 4]);
            afr[mt][3] = __float_as_uint(As[(r + 8) * 68 + kb + tig + 4]);
        }
        #pragma unroll
        for (int nt = 0; nt < 4; nt++) {
            int cn = n0 + nt * 8 + gid;
            bfr[nt][0] = __float_as_uint(Bs[cn * 68 + kb + tig]);
            bfr[nt][1] = __float_as_uint(Bs[cn * 68 + kb + tig + 4]);
        }
        #pragma unroll
        for (int mt = 0; mt < 2; mt++)
            #pragma unroll
            for (int nt = 0; nt < 4; nt++)
                mma_tf32(acc[mt][nt], afr[mt], bfr[nt]);
    }

    #pragma unroll
    for (int mt = 0; mt < 2; mt++) {
        int r = n * TT + t0 + m0 + mt * 16 + gid;
        #pragma unroll
        for (int nt = 0; nt < 4; nt++) {
            int cn = n0 + nt * 8 + tig * 2;
            float2 bv = *(const float2*)(bias + cn);
            *(float2*)&g_h[(size_t)r * DMM + cn] =
                make_float2(acc[mt][nt][0] + bv.x, acc[mt][nt][1] + bv.y);
            *(float2*)&g_h[(size_t)(r + 8) * DMM + cn] =
                make_float2(acc[mt][nt][2] + bv.x, acc[mt][nt][3] + bv.y);
        }
    }
}

// ---------------- in_proj GEMM: xi -> fp16, silu(z) -> fp16 ----------------
__global__ void __launch_bounds__(256) inproj_kernel(
    const float* __restrict__ B)
{
    const int BK = 16, K = DMM;
    __shared__ float As[2][128][BK + 4];
    __shared__ float Bs[2][64][BK + 4];

    int tid  = threadIdx.x;
    int bm   = blockIdx.x * 128, bn = blockIdx.y * 64;
    int warp = tid >> 5, lane = tid & 31;
    int gid  = lane >> 2, tig = lane & 3;
    int m0   = (warp & 3) * 32;
    int n0   = (warp >> 2) * 32;

    float acc[2][4][4];
    #pragma unroll
    for (int i = 0; i < 2; i++)
        #pragma unroll
        for (int j = 0; j < 4; j++)
            #pragma unroll
            for (int k = 0; k < 4; k++) acc[i][j][k] = 0.f;

    int arow = tid >> 1, akq = (tid & 1) * 8;
    int brow = tid >> 2, bkq = (tid & 3) * 4;
    const float* aptr = g_h + (size_t)(bm + arow) * K + akq;
    const float* bptr = B + (size_t)(bn + brow) * K + bkq;
    const int nk = K / BK;

    {
        uint32_t da0 = smem_u32(&As[0][arow][akq]);
        uint32_t da1 = smem_u32(&As[0][arow][akq + 4]);
        uint32_t db  = smem_u32(&Bs[0][brow][bkq]);
        asm volatile("cp.async.cg.shared.global [%0], [%1], 16;" :: "r"(da0), "l"(aptr));
        asm volatile("cp.async.cg.shared.global [%0], [%1], 16;" :: "r"(da1), "l"(aptr + 4));
        asm volatile("cp.async.cg.shared.global [%0], [%1], 16;" :: "r"(db),  "l"(bptr));
        asm volatile("cp.async.commit_group;");
    }

    for (int i = 0; i < nk; i++) {
        int buf = i & 1;
        asm volatile("cp.async.wait_group 0;");
        __syncthreads();
        if (i + 1 < nk) {
            int k0 = (i + 1) * BK;
            uint32_t da0 = smem_u32(&As[buf ^ 1][arow][akq]);
            uint32_t da1 = smem_u32(&As[buf ^ 1][arow][akq + 4]);
            uint32_t db  = smem_u32(&Bs[buf ^ 1][brow][bkq]);
            asm volatile("cp.async.cg.shared.global [%0], [%1], 16;" :: "r"(da0), "l"(aptr + k0));
            asm volatile("cp.async.cg.shared.global [%0], [%1], 16;" :: "r"(da1), "l"(aptr + k0 + 4));
            asm volatile("cp.async.cg.shared.global [%0], [%1], 16;" :: "r"(db),  "l"(bptr + k0));
            asm volatile("cp.async.commit_group;");
        }
        #pragma unroll
        for (int c = 0; c < 2; c++) {
            int kb = c * 8;
            uint32_t afr[2][4], bfr[4][2];
            #pragma unroll
            for (int mt = 0; mt < 2; mt++) {
                int r = m0 + mt * 16 + gid;
                afr[mt][0] = __float_as_uint(As[buf][r    ][kb + tig]);
                afr[mt][1] = __float_as_uint(As[buf][r + 8][kb + tig]);
                afr[mt][2] = __float_as_uint(As[buf][r    ][kb + tig + 4]);
                afr[mt][3] = __float_as_uint(As[buf][r + 8][kb + tig + 4]);
            }
            #pragma unroll
            for (int nt = 0; nt < 4; nt++) {
                int cn = n0 + nt * 8 + gid;
                bfr[nt][0] = __float_as_uint(Bs[buf][cn][kb + tig]);
                bfr[nt][1] = __float_as_uint(Bs[buf][cn][kb + tig + 4]);
            }
            #pragma unroll
            for (int mt = 0; mt < 2; mt++)
                #pragma unroll
                for (int nt = 0; nt < 4; nt++)
                    mma_tf32(acc[mt][nt], afr[mt], bfr[nt]);
        }
    }

    if (bn < DII) {
        __half2* dst = (__half2*)g_xih;
        #pragma unroll
        for (int mt = 0; mt < 2; mt++) {
            int r = bm + m0 + mt * 16 + gid;
            #pragma unroll
            for (int nt = 0; nt < 4; nt++) {
                int cn = bn + n0 + nt * 8 + tig * 2;
                dst[((size_t)r * DII + cn) >> 1] =
                    __floats2half2_rn(acc[mt][nt][0], acc[mt][nt][1]);
                dst[((size_t)(r + 8) * DII + cn) >> 1] =
                    __floats2half2_rn(acc[mt][nt][2], acc[mt][nt][3]);
            }
        }
    } else {
        #pragma unroll
        for (int mt = 0; mt < 2; mt++) {
            int r = bm + m0 + mt * 16 + gid;
            #pragma unroll
            for (int nt = 0; nt < 4; nt++) {
                int cn = (bn - DII) + n0 + nt * 8 + tig * 2;
                float s0 = acc[mt][nt][0], s1 = acc[mt][nt][1];
                float s2 = acc[mt][nt][2], s3 = acc[mt][nt][3];
                s0 = s0 / (1.f + __expf(-s0));
                s1 = s1 / (1.f + __expf(-s1));
                s2 = s2 / (1.f + __expf(-s2));
                s3 = s3 / (1.f + __expf(-s3));
                g_szh[(size_t)r * 128 + (cn >> 1)]       = __floats2half2_rn(s0, s1);
                g_szh[(size_t)(r + 8) * 128 + (cn >> 1)] = __floats2half2_rn(s2, s3);
            }
        }
    }
}

// ---- fused conv(smem,fp16)+silu -> fp16-HMMA x_proj GEMM -> coef; 256 thr, 32-t tile ----
#define USTR 264
__global__ void __launch_bounds__(256) convxproj_kernel(
    const float* __restrict__ cw, const float* __restrict__ cb,
    const float* __restrict__ dtw, const float* __restrict__ dtb, const float* __restrict__ Dv,
    const __half* __restrict__ xpwh)
{
    extern __shared__ char smc[];
    __half* us_h  = (__half*)smc;                      // [32][264]
    __half* Bsm_h = (__half*)(smc + CXT * USTR * 2);   // [40][264]
    float*  xds   = (float*)(smc + CXT * USTR * 2);    // reuse as [32][44]
    __half* halo  = (__half*)(smc + CXT * USTR * 2 + 40 * USTR * 2);  // [3][256]
    int tid = threadIdx.x;
    int n = blockIdx.x >> 3, t0 = (blockIdx.x & 7) * CXT;
    int R0 = n * TT + t0;

    // x_proj weights fp16: 1280 f4; 5 per thread
    #pragma unroll
    for (int i = 0; i < 5; i++) {
        int idx = tid + i * 256;
        int row = idx >> 5, c8 = (idx & 31) << 3;
        uint32_t dst = smem_u32(&Bsm_h[row * USTR + c8]);
        asm volatile("cp.async.cg.shared.global [%0], [%1], 16;" ::
                     "r"(dst), "l"(xpwh + (size_t)row * 256 + c8));
    }
    // xi tile fp16: 32x256 halves = 1024 f4; 4 per thread
    {
        const __half* src = g_xih + (size_t)R0 * DII;
        #pragma unroll
        for (int i = 0; i < 4; i++) {
            int idx = tid + i * 256;
            int row = idx >> 5, c8 = (idx & 31) << 3;
            uint32_t dst = smem_u32(&us_h[row * USTR + c8]);
            asm volatile("cp.async.cg.shared.global [%0], [%1], 16;"
                         :: "r"(dst), "l"(src + (size_t)row * DII + c8));
        }
    }
    // halo rows
    if (t0 >= 3) {
        if (tid < 96) {
            int row = tid >> 5, c8 = (tid & 31) << 3;
            uint32_t dst = smem_u32(&halo[row * 256 + c8]);
            asm volatile("cp.async.cg.shared.global [%0], [%1], 16;"
                         :: "r"(dst), "l"(g_xih + (size_t)(R0 - 3 + row) * DII + c8));
        }
    } else {
        if (tid < 96) *(float4*)&halo[tid * 8] = make_float4(0.f, 0.f, 0.f, 0.f);
    }
    asm volatile("cp.async.commit_group;");
    asm volatile("cp.async.wait_group 0;");
    __syncthreads();

    // conv+silu in place
    {
        int d = tid;
        float w0 = cw[d * 4], w1 = cw[d * 4 + 1], w2 = cw[d * 4 + 2], w3 = cw[d * 4 + 3];
        float bias = cb[d];
        float x0 = __half2float(halo[d]);
        float x1 = __half2float(halo[256 + d]);
        float x2 = __half2float(halo[512 + d]);
        #pragma unroll 4
        for (int tt = 0; tt < CXT; tt += 4) {
            float a0 = __half2float(us_h[(tt + 0) * USTR + d]);
            float a1 = __half2float(us_h[(tt + 1) * USTR + d]);
            float a2 = __half2float(us_h[(tt + 2) * USTR + d]);
            float a3 = __half2float(us_h[(tt + 3) * USTR + d]);
            float s;
            s = w0 * x0 + w1 * x1 + w2 * x2 + w3 * a0 + bias;
            us_h[(tt + 0) * USTR + d] = __float2half_rn(s / (1.f + __expf(-s)));
            s = w0 * x1 + w1 * x2 + w2 * a0 + w3 * a1 + bias;
            us_h[(tt + 1) * USTR + d] = __float2half_rn(s / (1.f + __expf(-s)));
            s = w0 * x2 + w1 * a0 + w2 * a1 + w3 * a2 + bias;
            us_h[(tt + 2) * USTR + d] = __float2half_rn(s / (1.f + __expf(-s)));
            s = w0 * a0 + w1 * a1 + w2 * a2 + w3 * a3 + bias;
            us_h[(tt + 3) * USTR + d] = __float2half_rn(s / (1.f + __expf(-s)));
            x0 = a1; x1 = a2; x2 = a3;
        }
    }
    __syncthreads();

    // fp16 HMMA GEMM: u[32x256] @ W[40x256]^T
    // 8 warps = 2(m: warp&1 -> m0 in {0,16}) x 4(col group wg=warp>>1).
    // wg g owns col-tile g (cols g*8..g*8+7); wg 0 also owns tile 4 (cols 32..39).
    int warp = tid >> 5, lane = tid & 31;
    int gid = lane >> 2, tig = lane & 3;
    int m0 = (warp & 1) * 16;
    int wg = warp >> 1;
    int nt2 = (wg == 0) ? 2 : 1;
    int cn0 = wg * 8, cn1 = 32;

    float acc[2][4];
    #pragma unroll
    for (int j = 0; j < 2; j++)
        #pragma unroll
        for (int k = 0; k < 4; k++) acc[j][k] = 0.f;

    #pragma unroll 4
    for (int kb = 0; kb < 256; kb += 16) {
        uint32_t afr[4], bfr[2][2];
        int r = m0 + gid;
        afr[0] = *(const uint32_t*)&us_h[r * USTR + kb + tig * 2];
        afr[1] = *(const uint32_t*)&us_h[(r + 8) * USTR + kb + tig * 2];
        afr[2] = *(const uint32_t*)&us_h[r * USTR + kb + tig * 2 + 8];
        afr[3] = *(const uint32_t*)&us_h[(r + 8) * USTR + kb + tig * 2 + 8];
        {
            int cn = cn0 + gid;
            bfr[0][0] = *(const uint32_t*)&Bsm_h[cn * USTR + kb + tig * 2];
            bfr[0][1] = *(const uint32_t*)&Bsm_h[cn * USTR + kb + tig * 2 + 8];
        }
        if (nt2 == 2) {
            int cn = cn1 + gid;
            bfr[1][0] = *(const uint32_t*)&Bsm_h[cn * USTR + kb + tig * 2];
            bfr[1][1] = *(const uint32_t*)&Bsm_h[cn * USTR + kb + tig * 2 + 8];
        }
        mma_f16(acc[0], afr, bfr[0]);
        if (nt2 == 2) mma_f16(acc[1], afr, bfr[1]);
    }

    int q  = tid & 63;
    int rh = tid >> 6;
    float wq[4][8];
    #pragma unroll
    for (int j = 0; j < 4; j++) {
        float4 wa = *(const float4*)(dtw + (size_t)(q * 4 + j) * 8);
        float4 wb = *(const float4*)(dtw + (size_t)(q * 4 + j) * 8 + 4);
        wq[j][0] = wa.x; wq[j][1] = wa.y; wq[j][2] = wa.z; wq[j][3] = wa.w;
        wq[j][4] = wb.x; wq[j][5] = wb.y; wq[j][6] = wb.z; wq[j][7] = wb.w;
    }
    float4 dtb4 = *(const float4*)(dtb + q * 4);
    float4 Dv4  = *(const float4*)(Dv + q * 4);
    float dtbs[4] = {dtb4.x, dtb4.y, dtb4.z, dtb4.w};
    float Dvs[4]  = {Dv4.x, Dv4.y, Dv4.z, Dv4.w};

    __syncthreads();   // GEMM reads of Bsm_h done before xds overwrite

    {
        int r = m0 + gid;
        {
            int cn = cn0 + tig * 2;
            *(float2*)&g_xdbl[(size_t)(R0 + r) * 40 + cn]     = make_float2(acc[0][0], acc[0][1]);
            *(float2*)&g_xdbl[(size_t)(R0 + r + 8) * 40 + cn] = make_float2(acc[0][2], acc[0][3]);
            *(float2*)&xds[r * 44 + cn]       = make_float2(acc[0][0], acc[0][1]);
            *(float2*)&xds[(r + 8) * 44 + cn] = make_float2(acc[0][2], acc[0][3]);
        }
        if (nt2 == 2) {
            int cn = cn1 + tig * 2;
            *(float2*)&g_xdbl[(size_t)(R0 + r) * 40 + cn]     = make_float2(acc[1][0], acc[1][1]);
            *(float2*)&g_xdbl[(size_t)(R0 + r + 8) * 40 + cn] = make_float2(acc[1][2], acc[1][3]);
            *(float2*)&xds[r * 44 + cn]       = make_float2(acc[1][0], acc[1][1]);
            *(float2*)&xds[(r + 8) * 44 + cn] = make_float2(acc[1][2], acc[1][3]);
        }
    }
    __syncthreads();

    // coef: 32 rows, rh in 0..3 owns 8 rows
    for (int i = 0; i < 8; i++) {
        int row = rh * 8 + i;
        float4 da = *(float4*)&xds[row * 44];
        float4 db = *(float4*)&xds[row * 44 + 4];
        __half2 ua = *(__half2*)&us_h[row * USTR + q * 4];
        __half2 ub = *(__half2*)&us_h[row * USTR + q * 4 + 2];
        float2 u01 = __half22float2(ua), u23 = __half22float2(ub);
        __half2 za = g_szh[(size_t)(R0 + row) * 128 + q * 2];
        __half2 zb = g_szh[(size_t)(R0 + row) * 128 + q * 2 + 1];
        float2 s01 = __half22float2(za), s23 = __half22float2(zb);
        float uu[4] = {u01.x, u01.y, u23.x, u23.y};
        float szv[4] = {s01.x, s01.y, s23.x, s23.y};
        #pragma unroll
        for (int j = 0; j < 4; j++) {
            float dtv = dtbs[j]
                + da.x * wq[j][0] + da.y * wq[j][1] + da.z * wq[j][2] + da.w * wq[j][3]
                + db.x * wq[j][4] + db.y * wq[j][5] + db.z * wq[j][6] + db.w * wq[j][7];
            float pp, delta;
            if (dtv > 15.f) { delta = dtv; pp = __expf(-dtv); }
            else {
                float e1 = __expf(dtv);
                pp = 1.f / (1.f + e1);
                delta = -__logf(pp);
            }
            size_t gidx = (size_t)(R0 + row) * DII + q * 4 + j;
            g_coefA[gidx] = make_float2(delta * uu[j], pp);
            g_coefB[gidx] = __floats2half2_rn(szv[j], uu[j] * Dvs[j]);
        }
    }
}

// ------- fused out_proj fp16-HMMA GEMM + residual + LayerNorm -------
__global__ void __launch_bounds__(256) outproj_ln_kernel(
    const __half* __restrict__ Bw,
    const float* __restrict__ nw, const float* __restrict__ nb)
{
    const int BK = 16, K = DII;
    __shared__ __half Ash[2][64][BK + 8];
    __shared__ __half Bsh[2][DMM][BK + 8];
    __shared__ float  Cs[64][DMM + 4];

    int tid  = threadIdx.x;
    int bm   = blockIdx.x * 64;
    int warp = tid >> 5, lane = tid & 31;
    int gid  = lane >> 2, tig = lane & 3;
    int m0   = (warp & 1) * 32;
    int n0   = (warp >> 1) * 32;

    float acc[2][4][4];
    #pragma unroll
    for (int i = 0; i < 2; i++)
        #pragma unroll
        for (int j = 0; j < 4; j++)
            #pragma unroll
            for (int k = 0; k < 4; k++) acc[i][j][k] = 0.f;

    int arow = tid >> 1, ahq = (tid & 1) * 8;
    int brow = tid >> 1, bhq = (tid & 1) * 8;
    const __half* aptr = g_ymh + (size_t)(bm + arow) * K + ahq;
    const __half* bptr = Bw + (size_t)brow * K + bhq;
    const int nk = K / BK;

    {
        if (tid < 128) {
            uint32_t da = smem_u32(&Ash[0][arow][ahq]);
            asm volatile("cp.async.cg.shared.global [%0], [%1], 16;" :: "r"(da), "l"(aptr));
        }
        uint32_t db = smem_u32(&Bsh[0][brow][bhq]);
        asm volatile("cp.async.cg.shared.global [%0], [%1], 16;" :: "r"(db), "l"(bptr));
        asm volatile("cp.async.commit_group;");
    }

    for (int i = 0; i < nk; i++) {
        int buf = i & 1;
        asm volatile("cp.async.wait_group 0;");
        __syncthreads();
        if (i + 1 < nk) {
            int k0 = (i + 1) * BK;
            if (tid < 128) {
                uint32_t da = smem_u32(&Ash[buf ^ 1][arow][ahq]);
                asm volatile("cp.async.cg.shared.global [%0], [%1], 16;" :: "r"(da), "l"(aptr + k0));
            }
            uint32_t db = smem_u32(&Bsh[buf ^ 1][brow][bhq]);
            asm volatile("cp.async.cg.shared.global [%0], [%1], 16;" :: "r"(db), "l"(bptr + k0));
            asm volatile("cp.async.commit_group;");
        }
        uint32_t afr[2][4], bfr[4][2];
        #pragma unroll
        for (int mt = 0; mt < 2; mt++) {
            int r = m0 + mt * 16 + gid;
            afr[mt][0] = *(const uint32_t*)&Ash[buf][r    ][tig * 2];
            afr[mt][1] = *(const uint32_t*)&Ash[buf][r + 8][tig * 2];
            afr[mt][2] = *(const uint32_t*)&Ash[buf][r    ][tig * 2 + 8];
            afr[mt][3] = *(const uint32_t*)&Ash[buf][r + 8][tig * 2 + 8];
        }
        #pragma unroll
        for (int nt = 0; nt < 4; nt++) {
            int cn = n0 + nt * 8 + gid;
            bfr[nt][0] = *(const uint32_t*)&Bsh[buf][cn][tig * 2];
            bfr[nt][1] = *(const uint32_t*)&Bsh[buf][cn][tig * 2 + 8];
        }
        #pragma unroll
        for (int mt = 0; mt < 2; mt++)
            #pragma unroll
            for (int nt = 0; nt < 4; nt++)
                mma_f16(acc[mt][nt], afr[mt], bfr[nt]);
    }

    #pragma unroll
    for (int mt = 0; mt < 2; mt++) {
        int r = m0 + mt * 16 + gid;
        #pragma unroll
        for (int nt = 0; nt < 4; nt++) {
            int cn = n0 + nt * 8 + tig * 2;
            *(float2*)&Cs[r    ][cn] = make_float2(acc[mt][nt][0], acc[mt][nt][1]);
            *(float2*)&Cs[r + 8][cn] = make_float2(acc[mt][nt][2], acc[mt][nt][3]);
        }
    }
    __syncthreads();

    float w0 = nw[lane], w1 = nw[lane + 32], w2 = nw[lane + 64], w3 = nw[lane + 96];
    float b0 = nb[lane], b1 = nb[lane + 32], b2 = nb[lane + 64], b3 = nb[lane + 96];
    for (int rr = warp * 8; rr < warp * 8 + 8; rr++) {
        size_t gr = (size_t)(bm + rr) * DMM;
        float v0 = Cs[rr][lane]      + g_h[gr + lane];
        float v1 = Cs[rr][lane + 32] + g_h[gr + lane + 32];
        float v2 = Cs[rr][lane + 64] + g_h[gr + lane + 64];
        float v3 = Cs[rr][lane + 96] + g_h[gr + lane + 96];
        float s = v0 + v1 + v2 + v3;
        float q = v0 * v0 + v1 * v1 + v2 * v2 + v3 * v3;
        #pragma unroll
        for (int o = 16; o; o >>= 1) {
            s += __shfl_xor_sync(0xffffffffu, s, o);
            q += __shfl_xor_sync(0xffffffffu, q, o);
        }
        float mu = s * (1.0f / DMM);
        float var = q * (1.0f / DMM) - mu * mu;
        float rs = rsqrtf(var + LNEPS);
        g_h[gr + lane]      = (v0 - mu) * rs * w0 + b0;
        g_h[gr + lane + 32] = (v1 - mu) * rs * w1 + b1;
        g_h[gr + lane + 64] = (v2 - mu) * rs * w2 + b2;
        g_h[gr + lane + 96] = (v3 - mu) * rs * w3 + b3;
    }
}

// ---------------- selective scan ----------------
__global__ void __launch_bounds__(128) scan_kernel(const float* __restrict__ alog)
{
    extern __shared__ float sm[];
    float2*  scfA = (float2*)sm;
    __half2* sszd = (__half2*)(sm + NBUF * CHK * 128 * 2);
    float*   sbc  = (float*)(sszd + NBUF * CHK * 128);

    int n = blockIdx.x, tid = threadIdx.x;
    int d = blockIdx.y * 128 + tid;
    int dbase = blockIdx.y * 128;

    auto load_chunk = [&](int c, int buf) {
        int T0 = c * CHK;
        const float2* srcA = g_coefA + (size_t)(n * TT + T0) * DII + dbase;
        #pragma unroll
        for (int i = 0; i < 8; i++) {
            int idx = tid + i * 128;
            int t = idx >> 6, cc = (idx & 63) * 2;
            uint32_t dst = smem_u32(&scfA[(buf * CHK + t) * 128 + cc]);
            asm volatile("cp.async.cg.shared.global [%0], [%1], 16;"
                :: "r"(dst), "l"(srcA + (size_t)t * DII + cc));
        }
        const __half2* srcB = g_coefB + (size_t)(n * TT + T0) * DII + dbase;
        #pragma unroll
        for (int i = 0; i < 4; i++) {
            int idx = tid + i * 128;
            int t = idx >> 5, cc = (idx & 31) * 4;
            uint32_t dst = smem_u32(&sszd[(buf * CHK + t) * 128 + cc]);
            asm volatile("cp.async.cg.shared.global [%0], [%1], 16;"
                :: "r"(dst), "l"(srcB + (size_t)t * DII + cc));
        }
        {
            int t = tid >> 3, j = tid & 7;
            uint32_t dst = smem_u32(&sbc[(buf * CHK + t) * 32 + j * 4]);
            asm volatile("cp.async.cg.shared.global [%0], [%1], 16;"
                :: "r"(dst), "l"(g_xdbl + (size_t)(n * TT + T0 + t) * 40 + 8 + j * 4));
        }
        asm volatile("cp.async.commit_group;");
    };

    load_chunk(0, 0);
    load_chunk(1, 1);

    float A[DSS];
    bool fastA = true;
    #pragma unroll
    for (int s = 0; s < DSS; s++) {
        A[s] = -__expf(alog[d * DSS + s]);
        fastA = fastA && (A[s] == -(float)(s + 1));
    }
    float hst[DSS];
    #pragma unroll
    for (int s = 0; s < DSS; s++) hst[s] = 0.f;

    size_t base_y = (size_t)n * TT * DII + d;

    for (int c = 0; c < NC; c++) {
        int buf = c & (NBUF - 1);
        if (c + 2 < NC) {
            load_chunk(c + 2, (c + 2) & (NBUF - 1));
            asm volatile("cp.async.wait_group 2;");
        } else if (c + 1 < NC) {
            asm volatile("cp.async.wait_group 1;");
        } else {
            asm volatile("cp.async.wait_group 0;");
        }
        __syncthreads();

        #pragma unroll 4
        for (int tt = 0; tt < CHK; tt++) {
            float2 cf = scfA[(buf * CHK + tt) * 128 + tid];
            __half2 sd = sszd[(buf * CHK + tt) * 128 + tid];
            const float4* bc = (const float4*)(sbc + (buf * CHK + tt) * 32);
            float4 B0 = bc[0], B1 = bc[1], B2 = bc[2], B3 = bc[3];
            float4 C0 = bc[4], C1 = bc[5], C2 = bc[6], C3 = bc[7];
            float Bf[16] = {B0.x,B0.y,B0.z,B0.w, B1.x,B1.y,B1.z,B1.w,
                            B2.x,B2.y,B2.z,B2.w, B3.x,B3.y,B3.z,B3.w};
            float Cf[16] = {C0.x,C0.y,C0.z,C0.w, C1.x,C1.y,C1.z,C1.w,
                            C2.x,C2.y,C2.z,C2.w, C3.x,C3.y,C3.z,C3.w};
            float du = cf.x, p = cf.y;
            float e[16];
            if (fastA) { epowers(p, e); }
            else {
                float delta = -__logf(p);
                #pragma unroll
                for (int s = 0; s < DSS; s++) e[s] = __expf(delta * A[s]);
            }
            float y0 = 0.f, y1 = 0.f, y2 = 0.f, y3 = 0.f;
            #pragma unroll
            for (int s = 0; s < DSS; s += 4) {
                hst[s]     = e[s]     * hst[s]     + du * Bf[s];
                hst[s + 1] = e[s + 1] * hst[s + 1] + du * Bf[s + 1];
                hst[s + 2] = e[s + 2] * hst[s + 2] + du * Bf[s + 2];
                hst[s + 3] = e[s + 3] * hst[s + 3] + du * Bf[s + 3];
                y0 += hst[s]     * Cf[s];
                y1 += hst[s + 1] * Cf[s + 1];
                y2 += hst[s + 2] * Cf[s + 2];
                y3 += hst[s + 3] * Cf[s + 3];
            }
            float2 g = __half22float2(sd);
            float y = ((y0 + y1) + (y2 + y3)) + g.y;
            g_ymh[base_y + (size_t)(c * CHK + tt) * DII] = __float2half_rn(y * g.x);
        }
        __syncthreads();
    }
}

// ---------------- final layernorm + mean over T ----------------
__global__ void __launch_bounds__(128) final_partial_kernel(
    const float* __restrict__ w, const float* __restrict__ b)
{
    int n = blockIdx.x, t0 = blockIdx.y * 64, d = threadIdx.x;
    float wd = w[d], bd = b[d], acc = 0.f;
    for (int tt = 0; tt < 64; tt++) {
        float v = g_h[(size_t)(n * TT + t0 + tt) * DMM + d];
        float mu, var;
        row_stats128(v, mu, var);
        acc += (v - mu) * rsqrtf(var + LNEPS) * wd + bd;
    }
    g_part[(size_t)(n * 4 + blockIdx.y) * DMM + d] = acc;
}

__global__ void __launch_bounds__(128) final_combine_kernel(float* __restrict__ out)
{
    int n = blockIdx.x, d = threadIdx.x;
    float s = g_part[(size_t)(n * 4 + 0) * DMM + d]
            + g_part[(size_t)(n * 4 + 1) * DMM + d]
            + g_part[(size_t)(n * 4 + 2) * DMM + d]
            + g_part[(size_t)(n * 4 + 3) * DMM + d];
    out[(size_t)n * DMM + d] = s * (1.0f / TT);
}

// ---------------- launch ----------------
extern "C" void kernel_launch(void* const* d_in, const int* in_sizes, int n_in,
                              void* d_out, int out_size)
{
    (void)in_sizes; (void)n_in; (void)out_size;
    const float* x     = (const float*)d_in[0];
    const float* inp_w = (const float*)d_in[1];
    const float* inp_b = (const float*)d_in[2];
    const float* ipw   = (const float*)d_in[3];
    const float* cw    = (const float*)d_in[4];
    const float* cb    = (const float*)d_in[5];
    const float* xpw   = (const float*)d_in[6];
    const float* dtw   = (const float*)d_in[7];
    const float* dtb   = (const float*)d_in[8];
    const float* alog  = (const float*)d_in[9];
    const float* Dv    = (const float*)d_in[10];
    const float* opw   = (const float*)d_in[11];
    const float* nw    = (const float*)d_in[12];
    const float* nb    = (const float*)d_in[13];
    const float* onw   = (const float*)d_in[14];
    const float* onb   = (const float*)d_in[15];
    float* out = (float*)d_out;

    __half *popwh, *pxpwh;
    cudaGetSymbolAddress((void**)&popwh, g_opwh);
    cudaGetSymbolAddress((void**)&pxpwh, g_xpwh);

    const int SMEM_IP = (64 * 68 + 128 * 68) * 4;
    const int SMEM_CX = CXT * USTR * 2 + 40 * USTR * 2 + 3 * 256 * 2;   // 39552
    const int SMEM_SC = NBUF * CHK * 128 * 8 + NBUF * CHK * 128 * 4 + NBUF * CHK * 32 * 4;
    cudaFuncSetAttribute(input_proj_mma,   cudaFuncAttributeMaxDynamicSharedMemorySize, SMEM_IP);
    cudaFuncSetAttribute(convxproj_kernel, cudaFuncAttributeMaxDynamicSharedMemorySize, SMEM_CX);
    cudaFuncSetAttribute(scan_kernel,      cudaFuncAttributeMaxDynamicSharedMemorySize, SMEM_SC);

    const int n_cvt = 2 * DMM * DII / 2 + 2 * 40 * DII / 2;
    cvt_weights_kernel<<<(n_cvt + 255) / 256, 256>>>(opw, xpw);
    input_proj_mma<<<dim3(NSEQ, 4), 256, SMEM_IP>>>(x, inp_w, inp_b);

    for (int l = 0; l < 2; l++) {
        inproj_kernel<<<dim3(ROWS / 128, 8), 256>>>(ipw + (size_t)l * 2 * DII * DMM);
        convxproj_kernel<<<NSEQ * 8, 256, SMEM_CX>>>(
            cw + (size_t)l * DII * 4, cb + (size_t)l * DII,
            dtw + (size_t)l * DII * DTRR, dtb + (size_t)l * DII, Dv + (size_t)l * DII,
            pxpwh + (size_t)l * 40 * DII);
        scan_kernel<<<dim3(NSEQ, 2), 128, SMEM_SC>>>(alog + (size_t)l * DII * DSS);
        outproj_ln_kernel<<<ROWS / 64, 256>>>(
            popwh + (size_t)l * DMM * DII, nw + (size_t)l * DMM, nb + (size_t)l * DMM);
    }

    final_partial_kernel<<<dim3(NSEQ, 4), 128>>>(onw, onb);
    final_combine_kernel<<<NSEQ, 128>>>(out);
}

// round 16
// speedup vs baseline: 1.0167x; 1.0167x over previous
#include <cuda_runtime.h>
#include <cuda_fp16.h>
#include <math.h>
#include <stdint.h>

#define NSEQ 64
#define TT   256
#define FF   64
#define DMM  128
#define DII  256
#define DSS  16
#define DTRR 8
#define ROWS (NSEQ*TT)
#define LNEPS 1e-5f
#define CHK  16
#define NBUF 4
#define NC   (TT/CHK)
#define CXT  32

// ---------------- scratch ----------------
__device__ float   g_h    [ROWS*DMM];     // residual stream fp32
__device__ __half  g_hh   [ROWS*DMM];     // fp16 copy for HMMA A-operand
__device__ __half  g_xih  [ROWS*DII];
__device__ __half2 g_szh  [ROWS*DII/2];
__device__ float   g_xdbl [ROWS*40];
__device__ float2  g_coefA[ROWS*DII];
__device__ __half2 g_coefB[ROWS*DII];
__device__ __half  g_ymh  [ROWS*DII];
__device__ __half  g_opwh [2*DMM*DII];
__device__ __half  g_xpwh [2*40*DII];
__device__ __half  g_ipwh [2*2*DII*DMM];  // in_proj weights fp16
__device__ float   g_part [NSEQ*4*DMM];

// ---------------- helpers ----------------
__device__ __forceinline__ uint32_t smem_u32(const void* p) {
    return (uint32_t)__cvta_generic_to_shared(p);
}
__device__ __forceinline__ void mma_tf32(float* c, const uint32_t* a, const uint32_t* b) {
    asm volatile(
        "mma.sync.aligned.m16n8k8.row.col.f32.tf32.tf32.f32 "
        "{%0,%1,%2,%3}, {%4,%5,%6,%7}, {%8,%9}, {%0,%1,%2,%3};"
        : "+f"(c[0]), "+f"(c[1]), "+f"(c[2]), "+f"(c[3])
        : "r"(a[0]), "r"(a[1]), "r"(a[2]), "r"(a[3]), "r"(b[0]), "r"(b[1]));
}
__device__ __forceinline__ void mma_f16(float* c, const uint32_t* a, const uint32_t* b) {
    asm volatile(
        "mma.sync.aligned.m16n8k16.row.col.f32.f16.f16.f32 "
        "{%0,%1,%2,%3}, {%4,%5,%6,%7}, {%8,%9}, {%0,%1,%2,%3};"
        : "+f"(c[0]), "+f"(c[1]), "+f"(c[2]), "+f"(c[3])
        : "r"(a[0]), "r"(a[1]), "r"(a[2]), "r"(a[3]), "r"(b[0]), "r"(b[1]));
}
__device__ __forceinline__ void row_stats128(float v, float& mu, float& var) {
    float s = v, q = v * v;
    #pragma unroll
    for (int o = 16; o; o >>= 1) {
        s += __shfl_down_sync(0xffffffffu, s, o);
        q += __shfl_down_sync(0xffffffffu, q, o);
    }
    __shared__ float ss[4], sq[4];
    int w = threadIdx.x >> 5;
    if ((threadIdx.x & 31) == 0) { ss[w] = s; sq[w] = q; }
    __syncthreads();
    s = ss[0] + ss[1] + ss[2] + ss[3];
    q = sq[0] + sq[1] + sq[2] + sq[3];
    __syncthreads();
    mu  = s * (1.0f / DMM);
    var = q * (1.0f / DMM) - mu * mu;
}
__device__ __forceinline__ void epowers(float p, float* e) {
    e[0] = p;
    e[1] = p * p;
    e[2] = e[1] * p;     e[3]  = e[1] * e[1];
    e[4] = e[3] * p;     e[5]  = e[3] * e[1];
    e[6] = e[3] * e[2];  e[7]  = e[3] * e[3];
    e[8] = e[7] * p;     e[9]  = e[7] * e[1];
    e[10] = e[7] * e[2]; e[11] = e[7] * e[3];
    e[12] = e[7] * e[4]; e[13] = e[7] * e[5];
    e[14] = e[7] * e[6]; e[15] = e[7] * e[7];
}

// ---------------- weight conversion: opw + xpw + ipw -> fp16 ----------------
__global__ void __launch_bounds__(256) cvt_weights_kernel(
    const float* __restrict__ opw, const float* __restrict__ xpw,
    const float* __restrict__ ipw)
{
    int idx = blockIdx.x * 256 + threadIdx.x;
    const int n_op = 2 * DMM * DII / 2;
    const int n_xp = 2 * 40 * DII / 2;
    const int n_ip = 2 * 2 * DII * DMM / 2;
    if (idx < n_op) {
        float2 v = *(const float2*)(opw + idx * 2);
        ((__half2*)g_opwh)[idx] = __floats2half2_rn(v.x, v.y);
    } else if (idx < n_op + n_xp) {
        int j = idx - n_op;
        float2 v = *(const float2*)(xpw + j * 2);
        ((__half2*)g_xpwh)[j] = __floats2half2_rn(v.x, v.y);
    } else if (idx < n_op + n_xp + n_ip) {
        int j = idx - n_op - n_xp;
        float2 v = *(const float2*)(ipw + j * 2);
        ((__half2*)g_ipwh)[j] = __floats2half2_rn(v.x, v.y);
    }
}

// ---------------- tensorized input projection (writes g_h fp32 + g_hh fp16) --------------
__global__ void __launch_bounds__(256) input_proj_mma(
    const float* __restrict__ x, const float* __restrict__ w, const float* __restrict__ bias)
{
    extern __shared__ float sm[];
    float* As = sm;
    float* Bs = sm + 64 * 68;
    int n = blockIdx.x, t0 = blockIdx.y * 64;
    int tid = threadIdx.x;

    #pragma unroll
    for (int p = 0; p < 4; p++) {
        int f = p * 16 + (tid >> 4), t4 = (tid & 15) * 4;
        float4 v = *(const float4*)(x + ((size_t)(n * FF + f)) * TT + t0 + t4);
        As[(t4 + 0) * 68 + f] = v.x;
        As[(t4 + 1) * 68 + f] = v.y;
        As[(t4 + 2) * 68 + f] = v.z;
        As[(t4 + 3) * 68 + f] = v.w;
    }
    #pragma unroll
    for (int i = 0; i < 8; i++) {
        int idx = tid + i * 256;
        int row = idx >> 4, c4 = (idx & 15) << 2;
        *(float4*)&Bs[row * 68 + c4] = *(const float4*)(w + row * 64 + c4);
    }
    __syncthreads();

    int warp = tid >> 5, lane = tid & 31;
    int gid = lane >> 2, tig = lane & 3;
    int m0 = (warp & 1) * 32, n0 = (warp >> 1) * 32;

    float acc[2][4][4];
    #pragma unroll
    for (int i = 0; i < 2; i++)
        #pragma unroll
        for (int j = 0; j < 4; j++)
            #pragma unroll
            for (int k = 0; k < 4; k++) acc[i][j][k] = 0.f;

    #pragma unroll
    for (int kb = 0; kb < 64; kb += 8) {
        uint32_t afr[2][4], bfr[4][2];
        #pragma unroll
        for (int mt = 0; mt < 2; mt++) {
            int r = m0 + mt * 16 + gid;
            afr[mt][0] = __float_as_uint(As[r * 68 + kb + tig]);
            afr[mt][1] = __float_as_uint(As[(r + 8) * 68 + kb + tig]);
            afr[mt][2] = __float_as_uint(As[r * 68 + kb + tig + 4]);
            afr[mt][3] = __float_as_uint(As[(r + 8) * 68 + kb + tig + 4]);
        }
        #pragma unroll
        for (int nt = 0; nt < 4; nt++) {
            int cn = n0 + nt * 8 + gid;
            bfr[nt][0] = __float_as_uint(Bs[cn * 68 + kb + tig]);
            bfr[nt][1] = __float_as_uint(Bs[cn * 68 + kb + tig + 4]);
        }
        #pragma unroll
        for (int mt = 0; mt < 2; mt++)
            #pragma unroll
            for (int nt = 0; nt < 4; nt++)
                mma_tf32(acc[mt][nt], afr[mt], bfr[nt]);
    }

    __half2* hh = (__half2*)g_hh;
    #pragma unroll
    for (int mt = 0; mt < 2; mt++) {
        int r = n * TT + t0 + m0 + mt * 16 + gid;
        #pragma unroll
        for (int nt = 0; nt < 4; nt++) {
            int cn = n0 + nt * 8 + tig * 2;
            float2 bv = *(const float2*)(bias + cn);
            float v0 = acc[mt][nt][0] + bv.x, v1 = acc[mt][nt][1] + bv.y;
            float v2 = acc[mt][nt][2] + bv.x, v3 = acc[mt][nt][3] + bv.y;
            *(float2*)&g_h[(size_t)r * DMM + cn]       = make_float2(v0, v1);
            *(float2*)&g_h[(size_t)(r + 8) * DMM + cn] = make_float2(v2, v3);
            hh[((size_t)r * DMM + cn) >> 1]       = __floats2half2_rn(v0, v1);
            hh[((size_t)(r + 8) * DMM + cn) >> 1] = __floats2half2_rn(v2, v3);
        }
    }
}

// ---------------- in_proj fp16-HMMA GEMM: xi -> fp16, silu(z) -> fp16 ----------------
__global__ void __launch_bounds__(256) inproj_kernel(
    const __half* __restrict__ Bw)
{
    const int BK = 16, K = DMM;
    __shared__ __half Ash[2][128][BK + 8];
    __shared__ __half Bsh[2][64][BK + 8];

    int tid  = threadIdx.x;
    int bm   = blockIdx.x * 128, bn = blockIdx.y * 64;
    int warp = tid >> 5, lane = tid & 31;
    int gid  = lane >> 2, tig = lane & 3;
    int m0   = (warp & 3) * 32;
    int n0   = (warp >> 2) * 32;

    float acc[2][4][4];
    #pragma unroll
    for (int i = 0; i < 2; i++)
        #pragma unroll
        for (int j = 0; j < 4; j++)
            #pragma unroll
            for (int k = 0; k < 4; k++) acc[i][j][k] = 0.f;

    int arow = tid >> 1, ahq = (tid & 1) * 8;   // 128 rows x 16 halves, 2 thr/row
    const __half* aptr = g_hh + (size_t)(bm + arow) * K + ahq;
    const __half* bptr = Bw + (size_t)(bn + arow) * K + ahq;   // rows 0..63 used (tid<128)
    const int nk = K / BK;   // 8

    {
        uint32_t da = smem_u32(&Ash[0][arow][ahq]);
        asm volatile("cp.async.cg.shared.global [%0], [%1], 16;" :: "r"(da), "l"(aptr));
        if (tid < 128) {
            uint32_t db = smem_u32(&Bsh[0][arow][ahq]);
            asm volatile("cp.async.cg.shared.global [%0], [%1], 16;" :: "r"(db), "l"(bptr));
        }
        asm volatile("cp.async.commit_group;");
    }

    for (int i = 0; i < nk; i++) {
        int buf = i & 1;
        asm volatile("cp.async.wait_group 0;");
        __syncthreads();
        if (i + 1 < nk) {
            int k0 = (i + 1) * BK;
            uint32_t da = smem_u32(&Ash[buf ^ 1][arow][ahq]);
            asm volatile("cp.async.cg.shared.global [%0], [%1], 16;" :: "r"(da), "l"(aptr + k0));
            if (tid < 128) {
                uint32_t db = smem_u32(&Bsh[buf ^ 1][arow][ahq]);
                asm volatile("cp.async.cg.shared.global [%0], [%1], 16;" :: "r"(db), "l"(bptr + k0));
            }
            asm volatile("cp.async.commit_group;");
        }
        uint32_t afr[2][4], bfr[4][2];
        #pragma unroll
        for (int mt = 0; mt < 2; mt++) {
            int r = m0 + mt * 16 + gid;
            afr[mt][0] = *(const uint32_t*)&Ash[buf][r    ][tig * 2];
            afr[mt][1] = *(const uint32_t*)&Ash[buf][r + 8][tig * 2];
            afr[mt][2] = *(const uint32_t*)&Ash[buf][r    ][tig * 2 + 8];
            afr[mt][3] = *(const uint32_t*)&Ash[buf][r + 8][tig * 2 + 8];
        }
        #pragma unroll
        for (int nt = 0; nt < 4; nt++) {
            int cn = n0 + nt * 8 + gid;
            bfr[nt][0] = *(const uint32_t*)&Bsh[buf][cn][tig * 2];
            bfr[nt][1] = *(const uint32_t*)&Bsh[buf][cn][tig * 2 + 8];
        }
        #pragma unroll
        for (int mt = 0; mt < 2; mt++)
            #pragma unroll
            for (int nt = 0; nt < 4; nt++)
                mma_f16(acc[mt][nt], afr[mt], bfr[nt]);
    }

    if (bn < DII) {
        __half2* dst = (__half2*)g_xih;
        #pragma unroll
        for (int mt = 0; mt < 2; mt++) {
            int r = bm + m0 + mt * 16 + gid;
            #pragma unroll
            for (int nt = 0; nt < 4; nt++) {
                int cn = bn + n0 + nt * 8 + tig * 2;
                dst[((size_t)r * DII + cn) >> 1] =
                    __floats2half2_rn(acc[mt][nt][0], acc[mt][nt][1]);
                dst[((size_t)(r + 8) * DII + cn) >> 1] =
                    __floats2half2_rn(acc[mt][nt][2], acc[mt][nt][3]);
            }
        }
    } else {
        #pragma unroll
        for (int mt = 0; mt < 2; mt++) {
            int r = bm + m0 + mt * 16 + gid;
            #pragma unroll
            for (int nt = 0; nt < 4; nt++) {
                int cn = (bn - DII) + n0 + nt * 8 + tig * 2;
                float s0 = acc[mt][nt][0], s1 = acc[mt][nt][1];
                float s2 = acc[mt][nt][2], s3 = acc[mt][nt][3];
                s0 = s0 / (1.f + __expf(-s0));
                s1 = s1 / (1.f + __expf(-s1));
                s2 = s2 / (1.f + __expf(-s2));
                s3 = s3 / (1.f + __expf(-s3));
                g_szh[(size_t)r * 128 + (cn >> 1)]       = __floats2half2_rn(s0, s1);
                g_szh[(size_t)(r + 8) * 128 + (cn >> 1)] = __floats2half2_rn(s2, s3);
            }
        }
    }
}

// ---- fused conv(smem,fp16)+silu -> fp16-HMMA x_proj GEMM -> coef; 256 thr, 32-t tile ----
#define USTR 264
__global__ void __launch_bounds__(256) convxproj_kernel(
    const float* __restrict__ cw, const float* __restrict__ cb,
    const float* __restrict__ dtw, const float* __restrict__ dtb, const float* __restrict__ Dv,
    const __half* __restrict__ xpwh)
{
    extern __shared__ char smc[];
    __half* us_h  = (__half*)smc;
    __half* Bsm_h = (__half*)(smc + CXT * USTR * 2);
    float*  xds   = (float*)(smc + CXT * USTR * 2);
    __half* halo  = (__half*)(smc + CXT * USTR * 2 + 40 * USTR * 2);
    int tid = threadIdx.x;
    int n = blockIdx.x >> 3, t0 = (blockIdx.x & 7) * CXT;
    int R0 = n * TT + t0;

    #pragma unroll
    for (int i = 0; i < 5; i++) {
        int idx = tid + i * 256;
        int row = idx >> 5, c8 = (idx & 31) << 3;
        uint32_t dst = smem_u32(&Bsm_h[row * USTR + c8]);
        asm volatile("cp.async.cg.shared.global [%0], [%1], 16;" ::
                     "r"(dst), "l"(xpwh + (size_t)row * 256 + c8));
    }
    {
        const __half* src = g_xih + (size_t)R0 * DII;
        #pragma unroll
        for (int i = 0; i < 4; i++) {
            int idx = tid + i * 256;
            int row = idx >> 5, c8 = (idx & 31) << 3;
            uint32_t dst = smem_u32(&us_h[row * USTR + c8]);
            asm volatile("cp.async.cg.shared.global [%0], [%1], 16;"
                         :: "r"(dst), "l"(src + (size_t)row * DII + c8));
        }
    }
    if (t0 >= 3) {
        if (tid < 96) {
            int row = tid >> 5, c8 = (tid & 31) << 3;
            uint32_t dst = smem_u32(&halo[row * 256 + c8]);
            asm volatile("cp.async.cg.shared.global [%0], [%1], 16;"
                         :: "r"(dst), "l"(g_xih + (size_t)(R0 - 3 + row) * DII + c8));
        }
    } else {
        if (tid < 96) *(float4*)&halo[tid * 8] = make_float4(0.f, 0.f, 0.f, 0.f);
    }
    asm volatile("cp.async.commit_group;");
    asm volatile("cp.async.wait_group 0;");
    __syncthreads();

    {
        int d = tid;
        float w0 = cw[d * 4], w1 = cw[d * 4 + 1], w2 = cw[d * 4 + 2], w3 = cw[d * 4 + 3];
        float bias = cb[d];
        float x0 = __half2float(halo[d]);
        float x1 = __half2float(halo[256 + d]);
        float x2 = __half2float(halo[512 + d]);
        #pragma unroll 4
        for (int tt = 0; tt < CXT; tt += 4) {
            float a0 = __half2float(us_h[(tt + 0) * USTR + d]);
            float a1 = __half2float(us_h[(tt + 1) * USTR + d]);
            float a2 = __half2float(us_h[(tt + 2) * USTR + d]);
            float a3 = __half2float(us_h[(tt + 3) * USTR + d]);
            float s;
            s = w0 * x0 + w1 * x1 + w2 * x2 + w3 * a0 + bias;
            us_h[(tt + 0) * USTR + d] = __float2half_rn(s / (1.f + __expf(-s)));
            s = w0 * x1 + w1 * x2 + w2 * a0 + w3 * a1 + bias;
            us_h[(tt + 1) * USTR + d] = __float2half_rn(s / (1.f + __expf(-s)));
            s = w0 * x2 + w1 * a0 + w2 * a1 + w3 * a2 + bias;
            us_h[(tt + 2) * USTR + d] = __float2half_rn(s / (1.f + __expf(-s)));
            s = w0 * a0 + w1 * a1 + w2 * a2 + w3 * a3 + bias;
            us_h[(tt + 3) * USTR + d] = __float2half_rn(s / (1.f + __expf(-s)));
            x0 = a1; x1 = a2; x2 = a3;
        }
    }
    __syncthreads();

    int warp = tid >> 5, lane = tid & 31;
    int gid = lane >> 2, tig = lane & 3;
    int m0 = (warp & 1) * 16;
    int wg = warp >> 1;
    int nt2 = (wg == 0) ? 2 : 1;
    int cn0 = wg * 8, cn1 = 32;

    float acc[2][4];
    #pragma unroll
    for (int j = 0; j < 2; j++)
        #pragma unroll
        for (int k = 0; k < 4; k++) acc[j][k] = 0.f;

    #pragma unroll 4
    for (int kb = 0; kb < 256; kb += 16) {
        uint32_t afr[4], bfr[2][2];
        int r = m0 + gid;
        afr[0] = *(const uint32_t*)&us_h[r * USTR + kb + tig * 2];
        afr[1] = *(const uint32_t*)&us_h[(r + 8) * USTR + kb + tig * 2];
        afr[2] = *(const uint32_t*)&us_h[r * USTR + kb + tig * 2 + 8];
        afr[3] = *(const uint32_t*)&us_h[(r + 8) * USTR + kb + tig * 2 + 8];
        {
            int cn = cn0 + gid;
            bfr[0][0] = *(const uint32_t*)&Bsm_h[cn * USTR + kb + tig * 2];
            bfr[0][1] = *(const uint32_t*)&Bsm_h[cn * USTR + kb + tig * 2 + 8];
        }
        if (nt2 == 2) {
            int cn = cn1 + gid;
            bfr[1][0] = *(const uint32_t*)&Bsm_h[cn * USTR + kb + tig * 2];
            bfr[1][1] = *(const uint32_t*)&Bsm_h[cn * USTR + kb + tig * 2 + 8];
        }
        mma_f16(acc[0], afr, bfr[0]);
        if (nt2 == 2) mma_f16(acc[1], afr, bfr[1]);
    }

    int q  = tid & 63;
    int rh = tid >> 6;
    float wq[4][8];
    #pragma unroll
    for (int j = 0; j < 4; j++) {
        float4 wa = *(const float4*)(dtw + (size_t)(q * 4 + j) * 8);
        float4 wb = *(const float4*)(dtw + (size_t)(q * 4 + j) * 8 + 4);
        wq[j][0] = wa.x; wq[j][1] = wa.y; wq[j][2] = wa.z; wq[j][3] = wa.w;
        wq[j][4] = wb.x; wq[j][5] = wb.y; wq[j][6] = wb.z; wq[j][7] = wb.w;
    }
    float4 dtb4 = *(const float4*)(dtb + q * 4);
    float4 Dv4  = *(const float4*)(Dv + q * 4);
    float dtbs[4] = {dtb4.x, dtb4.y, dtb4.z, dtb4.w};
    float Dvs[4]  = {Dv4.x, Dv4.y, Dv4.z, Dv4.w};

    __syncthreads();

    {
        int r = m0 + gid;
        {
            int cn = cn0 + tig * 2;
            *(float2*)&g_xdbl[(size_t)(R0 + r) * 40 + cn]     = make_float2(acc[0][0], acc[0][1]);
            *(float2*)&g_xdbl[(size_t)(R0 + r + 8) * 40 + cn] = make_float2(acc[0][2], acc[0][3]);
            *(float2*)&xds[r * 44 + cn]       = make_float2(acc[0][0], acc[0][1]);
            *(float2*)&xds[(r + 8) * 44 + cn] = make_float2(acc[0][2], acc[0][3]);
        }
        if (nt2 == 2) {
            int cn = cn1 + tig * 2;
            *(float2*)&g_xdbl[(size_t)(R0 + r) * 40 + cn]     = make_float2(acc[1][0], acc[1][1]);
            *(float2*)&g_xdbl[(size_t)(R0 + r + 8) * 40 + cn] = make_float2(acc[1][2], acc[1][3]);
            *(float2*)&xds[r * 44 + cn]       = make_float2(acc[1][0], acc[1][1]);
            *(float2*)&xds[(r + 8) * 44 + cn] = make_float2(acc[1][2], acc[1][3]);
        }
    }
    __syncthreads();

    for (int i = 0; i < 8; i++) {
        int row = rh * 8 + i;
        float4 da = *(float4*)&xds[row * 44];
        float4 db = *(float4*)&xds[row * 44 + 4];
        __half2 ua = *(__half2*)&us_h[row * USTR + q * 4];
        __half2 ub = *(__half2*)&us_h[row * USTR + q * 4 + 2];
        float2 u01 = __half22float2(ua), u23 = __half22float2(ub);
        __half2 za = g_szh[(size_t)(R0 + row) * 128 + q * 2];
        __half2 zb = g_szh[(size_t)(R0 + row) * 128 + q * 2 + 1];
        float2 s01 = __half22float2(za), s23 = __half22float2(zb);
        float uu[4] = {u01.x, u01.y, u23.x, u23.y};
        float szv[4] = {s01.x, s01.y, s23.x, s23.y};
        #pragma unroll
        for (int j = 0; j < 4; j++) {
            float dtv = dtbs[j]
                + da.x * wq[j][0] + da.y * wq[j][1] + da.z * wq[j][2] + da.w * wq[j][3]
                + db.x * wq[j][4] + db.y * wq[j][5] + db.z * wq[j][6] + db.w * wq[j][7];
            float pp, delta;
            if (dtv > 15.f) { delta = dtv; pp = __expf(-dtv); }
            else {
                float e1 = __expf(dtv);
                pp = 1.f / (1.f + e1);
                delta = -__logf(pp);
            }
            size_t gidx = (size_t)(R0 + row) * DII + q * 4 + j;
            g_coefA[gidx] = make_float2(delta * uu[j], pp);
            g_coefB[gidx] = __floats2half2_rn(szv[j], uu[j] * Dvs[j]);
        }
    }
}

// ------- fused out_proj fp16-HMMA GEMM + residual + LayerNorm (writes g_h + g_hh) -------
__global__ void __launch_bounds__(256) outproj_ln_kernel(
    const __half* __restrict__ Bw,
    const float* __restrict__ nw, const float* __restrict__ nb)
{
    const int BK = 16, K = DII;
    __shared__ __half Ash[2][64][BK + 8];
    __shared__ __half Bsh[2][DMM][BK + 8];
    __shared__ float  Cs[64][DMM + 4];

    int tid  = threadIdx.x;
    int bm   = blockIdx.x * 64;
    int warp = tid >> 5, lane = tid & 31;
    int gid  = lane >> 2, tig = lane & 3;
    int m0   = (warp & 1) * 32;
    int n0   = (warp >> 1) * 32;

    float acc[2][4][4];
    #pragma unroll
    for (int i = 0; i < 2; i++)
        #pragma unroll
        for (int j = 0; j < 4; j++)
            #pragma unroll
            for (int k = 0; k < 4; k++) acc[i][j][k] = 0.f;

    int arow = tid >> 1, ahq = (tid & 1) * 8;
    int brow = tid >> 1, bhq = (tid & 1) * 8;
    const __half* aptr = g_ymh + (size_t)(bm + arow) * K + ahq;
    const __half* bptr = Bw + (size_t)brow * K + bhq;
    const int nk = K / BK;

    {
        if (tid < 128) {
            uint32_t da = smem_u32(&Ash[0][arow][ahq]);
            asm volatile("cp.async.cg.shared.global [%0], [%1], 16;" :: "r"(da), "l"(aptr));
        }
        uint32_t db = smem_u32(&Bsh[0][brow][bhq]);
        asm volatile("cp.async.cg.shared.global [%0], [%1], 16;" :: "r"(db), "l"(bptr));
        asm volatile("cp.async.commit_group;");
    }

    for (int i = 0; i < nk; i++) {
        int buf = i & 1;
        asm volatile("cp.async.wait_group 0;");
        __syncthreads();
        if (i + 1 < nk) {
            int k0 = (i + 1) * BK;
            if (tid < 128) {
                uint32_t da = smem_u32(&Ash[buf ^ 1][arow][ahq]);
                asm volatile("cp.async.cg.shared.global [%0], [%1], 16;" :: "r"(da), "l"(aptr + k0));
            }
            uint32_t db = smem_u32(&Bsh[buf ^ 1][brow][bhq]);
            asm volatile("cp.async.cg.shared.global [%0], [%1], 16;" :: "r"(db), "l"(bptr + k0));
            asm volatile("cp.async.commit_group;");
        }
        uint32_t afr[2][4], bfr[4][2];
        #pragma unroll
        for (int mt = 0; mt < 2; mt++) {
            int r = m0 + mt * 16 + gid;
            afr[mt][0] = *(const uint32_t*)&Ash[buf][r    ][tig * 2];
            afr[mt][1] = *(const uint32_t*)&Ash[buf][r + 8][tig * 2];
            afr[mt][2] = *(const uint32_t*)&Ash[buf][r    ][tig * 2 + 8];
            afr[mt][3] = *(const uint32_t*)&Ash[buf][r + 8][tig * 2 + 8];
        }
        #pragma unroll
        for (int nt = 0; nt < 4; nt++) {
            int cn = n0 + nt * 8 + gid;
            bfr[nt][0] = *(const uint32_t*)&Bsh[buf][cn][tig * 2];
            bfr[nt][1] = *(const uint32_t*)&Bsh[buf][cn][tig * 2 + 8];
        }
        #pragma unroll
        for (int mt = 0; mt < 2; mt++)
            #pragma unroll
            for (int nt = 0; nt < 4; nt++)
                mma_f16(acc[mt][nt], afr[mt], bfr[nt]);
    }

    #pragma unroll
    for (int mt = 0; mt < 2; mt++) {
        int r = m0 + mt * 16 + gid;
        #pragma unroll
        for (int nt = 0; nt < 4; nt++) {
            int cn = n0 + nt * 8 + tig * 2;
            *(float2*)&Cs[r    ][cn] = make_float2(acc[mt][nt][0], acc[mt][nt][1]);
            *(float2*)&Cs[r + 8][cn] = make_float2(acc[mt][nt][2], acc[mt][nt][3]);
        }
    }
    __syncthreads();

    float w0 = nw[lane], w1 = nw[lane + 32], w2 = nw[lane + 64], w3 = nw[lane + 96];
    float b0 = nb[lane], b1 = nb[lane + 32], b2 = nb[lane + 64], b3 = nb[lane + 96];
    for (int rr = warp * 8; rr < warp * 8 + 8; rr++) {
        size_t gr = (size_t)(bm + rr) * DMM;
        float v0 = Cs[rr][lane]      + g_h[gr + lane];
        float v1 = Cs[rr][lane + 32] + g_h[gr + lane + 32];
        float v2 = Cs[rr][lane + 64] + g_h[gr + lane + 64];
        float v3 = Cs[rr][lane + 96] + g_h[gr + lane + 96];
        float s = v0 + v1 + v2 + v3;
        float q = v0 * v0 + v1 * v1 + v2 * v2 + v3 * v3;
        #pragma unroll
        for (int o = 16; o; o >>= 1) {
            s += __shfl_xor_sync(0xffffffffu, s, o);
            q += __shfl_xor_sync(0xffffffffu, q, o);
        }
        float mu = s * (1.0f / DMM);
        float var = q * (1.0f / DMM) - mu * mu;
        float rs = rsqrtf(var + LNEPS);
        float h0 = (v0 - mu) * rs * w0 + b0;
        float h1 = (v1 - mu) * rs * w1 + b1;
        float h2 = (v2 - mu) * rs * w2 + b2;
        float h3 = (v3 - mu) * rs * w3 + b3;
        g_h[gr + lane]      = h0;
        g_h[gr + lane + 32] = h1;
        g_h[gr + lane + 64] = h2;
        g_h[gr + lane + 96] = h3;
        g_hh[gr + lane]      = __float2half_rn(h0);
        g_hh[gr + lane + 32] = __float2half_rn(h1);
        g_hh[gr + lane + 64] = __float2half_rn(h2);
        g_hh[gr + lane + 96] = __float2half_rn(h3);
    }
}

// ---------------- selective scan ----------------
__global__ void __launch_bounds__(128) scan_kernel(const float* __restrict__ alog)
{
    extern __shared__ float sm[];
    float2*  scfA = (float2*)sm;
    __half2* sszd = (__half2*)(sm + NBUF * CHK * 128 * 2);
    float*   sbc  = (float*)(sszd + NBUF * CHK * 128);

    int n = blockIdx.x, tid = threadIdx.x;
    int d = blockIdx.y * 128 + tid;
    int dbase = blockIdx.y * 128;

    auto load_chunk = [&](int c, int buf) {
        int T0 = c * CHK;
        const float2* srcA = g_coefA + (size_t)(n * TT + T0) * DII + dbase;
        #pragma unroll
        for (int i = 0; i < 8; i++) {
            int idx = tid + i * 128;
            int t = idx >> 6, cc = (idx & 63) * 2;
            uint32_t dst = smem_u32(&scfA[(buf * CHK + t) * 128 + cc]);
            asm volatile("cp.async.cg.shared.global [%0], [%1], 16;"
                :: "r"(dst), "l"(srcA + (size_t)t * DII + cc));
        }
        const __half2* srcB = g_coefB + (size_t)(n * TT + T0) * DII + dbase;
        #pragma unroll
        for (int i = 0; i < 4; i++) {
            int idx = tid + i * 128;
            int t = idx >> 5, cc = (idx & 31) * 4;
            uint32_t dst = smem_u32(&sszd[(buf * CHK + t) * 128 + cc]);
            asm volatile("cp.async.cg.shared.global [%0], [%1], 16;"
                :: "r"(dst), "l"(srcB + (size_t)t * DII + cc));
        }
        {
            int t = tid >> 3, j = tid & 7;
            uint32_t dst = smem_u32(&sbc[(buf * CHK + t) * 32 + j * 4]);
            asm volatile("cp.async.cg.shared.global [%0], [%1], 16;"
                :: "r"(dst), "l"(g_xdbl + (size_t)(n * TT + T0 + t) * 40 + 8 + j * 4));
        }
        asm volatile("cp.async.commit_group;");
    };

    load_chunk(0, 0);
    load_chunk(1, 1);

    float A[DSS];
    bool fastA = true;
    #pragma unroll
    for (int s = 0; s < DSS; s++) {
        A[s] = -__expf(alog[d * DSS + s]);
        fastA = fastA && (A[s] == -(float)(s + 1));
    }
    float hst[DSS];
    #pragma unroll
    for (int s = 0; s < DSS; s++) hst[s] = 0.f;

    size_t base_y = (size_t)n * TT * DII + d;

    for (int c = 0; c < NC; c++) {
        int buf = c & (NBUF - 1);
        if (c + 2 < NC) {
            load_chunk(c + 2, (c + 2) & (NBUF - 1));
            asm volatile("cp.async.wait_group 2;");
        } else if (c + 1 < NC) {
            asm volatile("cp.async.wait_group 1;");
        } else {
            asm volatile("cp.async.wait_group 0;");
        }
        __syncthreads();

        #pragma unroll 4
        for (int tt = 0; tt < CHK; tt++) {
            float2 cf = scfA[(buf * CHK + tt) * 128 + tid];
            __half2 sd = sszd[(buf * CHK + tt) * 128 + tid];
            const float4* bc = (const float4*)(sbc + (buf * CHK + tt) * 32);
            float4 B0 = bc[0], B1 = bc[1], B2 = bc[2], B3 = bc[3];
            float4 C0 = bc[4], C1 = bc[5], C2 = bc[6], C3 = bc[7];
            float Bf[16] = {B0.x,B0.y,B0.z,B0.w, B1.x,B1.y,B1.z,B1.w,
                            B2.x,B2.y,B2.z,B2.w, B3.x,B3.y,B3.z,B3.w};
            float Cf[16] = {C0.x,C0.y,C0.z,C0.w, C1.x,C1.y,C1.z,C1.w,
                            C2.x,C2.y,C2.z,C2.w, C3.x,C3.y,C3.z,C3.w};
            float du = cf.x, p = cf.y;
            float e[16];
            if (fastA) { epowers(p, e); }
            else {
                float delta = -__logf(p);
                #pragma unroll
                for (int s = 0; s < DSS; s++) e[s] = __expf(delta * A[s]);
            }
            float y0 = 0.f, y1 = 0.f, y2 = 0.f, y3 = 0.f;
            #pragma unroll
            for (int s = 0; s < DSS; s += 4) {
                hst[s]     = e[s]     * hst[s]     + du * Bf[s];
                hst[s + 1] = e[s + 1] * hst[s + 1] + du * Bf[s + 1];
                hst[s + 2] = e[s + 2] * hst[s + 2] + du * Bf[s + 2];
                hst[s + 3] = e[s + 3] * hst[s + 3] + du * Bf[s + 3];
                y0 += hst[s]     * Cf[s];
                y1 += hst[s + 1] * Cf[s + 1];
                y2 += hst[s + 2] * Cf[s + 2];
                y3 += hst[s + 3] * Cf[s + 3];
            }
            float2 g = __half22float2(sd);
            float y = ((y0 + y1) + (y2 + y3)) + g.y;
            g_ymh[base_y + (size_t)(c * CHK + tt) * DII] = __float2half_rn(y * g.x);
        }
        __syncthreads();
    }
}

// ---------------- final layernorm + mean over T ----------------
__global__ void __launch_bounds__(128) final_partial_kernel(
    const float* __restrict__ w, const float* __restrict__ b)
{
    int n = blockIdx.x, t0 = blockIdx.y * 64, d = threadIdx.x;
    float wd = w[d], bd = b[d], acc = 0.f;
    for (int tt = 0; tt < 64; tt++) {
        float v = g_h[(size_t)(n * TT + t0 + tt) * DMM + d];
        float mu, var;
        row_stats128(v, mu, var);
        acc += (v - mu) * rsqrtf(var + LNEPS) * wd + bd;
    }
    g_part[(size_t)(n * 4 + blockIdx.y) * DMM + d] = acc;
}

__global__ void __launch_bounds__(128) final_combine_kernel(float* __restrict__ out)
{
    int n = blockIdx.x, d = threadIdx.x;
    float s = g_part[(size_t)(n * 4 + 0) * DMM + d]
            + g_part[(size_t)(n * 4 + 1) * DMM + d]
            + g_part[(size_t)(n * 4 + 2) * DMM + d]
            + g_part[(size_t)(n * 4 + 3) * DMM + d];
    out[(size_t)n * DMM + d] = s * (1.0f / TT);
}

// ---------------- launch ----------------
extern "C" void kernel_launch(void* const* d_in, const int* in_sizes, int n_in,
                              void* d_out, int out_size)
{
    (void)in_sizes; (void)n_in; (void)out_size;
    const float* x     = (const float*)d_in[0];
    const float* inp_w = (const float*)d_in[1];
    const float* inp_b = (const float*)d_in[2];
    const float* ipw   = (const float*)d_in[3];
    const float* cw    = (const float*)d_in[4];
    const float* cb    = (const float*)d_in[5];
    const float* xpw   = (const float*)d_in[6];
    const float* dtw   = (const float*)d_in[7];
    const float* dtb   = (const float*)d_in[8];
    const float* alog  = (const float*)d_in[9];
    const float* Dv    = (const float*)d_in[10];
    const float* opw   = (const float*)d_in[11];
    const float* nw    = (const float*)d_in[12];
    const float* nb    = (const float*)d_in[13];
    const float* onw   = (const float*)d_in[14];
    const float* onb   = (const float*)d_in[15];
    float* out = (float*)d_out;

    __half *popwh, *pxpwh, *pipwh;
    cudaGetSymbolAddress((void**)&popwh, g_opwh);
    cudaGetSymbolAddress((void**)&pxpwh, g_xpwh);
    cudaGetSymbolAddress((void**)&pipwh, g_ipwh);

    const int SMEM_IP = (64 * 68 + 128 * 68) * 4;
    const int SMEM_CX = CXT * USTR * 2 + 40 * USTR * 2 + 3 * 256 * 2;
    const int SMEM_SC = NBUF * CHK * 128 * 8 + NBUF * CHK * 128 * 4 + NBUF * CHK * 32 * 4;
    cudaFuncSetAttribute(input_proj_mma,   cudaFuncAttributeMaxDynamicSharedMemorySize, SMEM_IP);
    cudaFuncSetAttribute(convxproj_kernel, cudaFuncAttributeMaxDynamicSharedMemorySize, SMEM_CX);
    cudaFuncSetAttribute(scan_kernel,      cudaFuncAttributeMaxDynamicSharedMemorySize, SMEM_SC);

    const int n_cvt = 2 * DMM * DII / 2 + 2 * 40 * DII / 2 + 2 * 2 * DII * DMM / 2;
    cvt_weights_kernel<<<(n_cvt + 255) / 256, 256>>>(opw, xpw, ipw);
    input_proj_mma<<<dim3(NSEQ, 4), 256, SMEM_IP>>>(x, inp_w, inp_b);

    for (int l = 0; l < 2; l++) {
        inproj_kernel<<<dim3(ROWS / 128, 8), 256>>>(pipwh + (size_t)l * 2 * DII * DMM);
        convxproj_kernel<<<NSEQ * 8, 256, SMEM_CX>>>(
            cw + (size_t)l * DII * 4, cb + (size_t)l * DII,
            dtw + (size_t)l * DII * DTRR, dtb + (size_t)l * DII, Dv + (size_t)l * DII,
            pxpwh + (size_t)l * 40 * DII);
        scan_kernel<<<dim3(NSEQ, 2), 128, SMEM_SC>>>(alog + (size_t)l * DII * DSS);
        outproj_ln_kernel<<<ROWS / 64, 256>>>(
            popwh + (size_t)l * DMM * DII, nw + (size_t)l * DMM, nb + (size_t)l * DMM);
    }

    final_partial_kernel<<<dim3(NSEQ, 4), 128>>>(onw, onb);
    final_combine_kernel<<<NSEQ, 128>>>(out);
}

// round 17
// speedup vs baseline: 1.0567x; 1.0394x over previous
#include <cuda_runtime.h>
#include <cuda_fp16.h>
#include <math.h>
#include <stdint.h>

#define NSEQ 64
#define TT   256
#define FF   64
#define DMM  128
#define DII  256
#define DSS  16
#define DTRR 8
#define ROWS (NSEQ*TT)
#define LNEPS 1e-5f
#define CHK  16
#define NBUF 4
#define NC   (TT/CHK)
#define CXT  32

// ---------------- scratch ----------------
__device__ float   g_h    [ROWS*DMM];
__device__ __half  g_hh   [ROWS*DMM];
__device__ __half  g_xih  [ROWS*DII];
__device__ __half2 g_szh  [ROWS*DII/2];
__device__ float   g_xdbl [ROWS*40];
__device__ float2  g_coefA[ROWS*DII];
__device__ __half2 g_coefB[ROWS*DII];
__device__ __half  g_ymh  [ROWS*DII];
__device__ __half  g_opwh [2*DMM*DII];
__device__ __half  g_xpwh [2*40*DII];
__device__ __half  g_ipwh [2*2*DII*DMM];
__device__ float   g_part [NSEQ*4*DMM];

// ---------------- helpers ----------------
__device__ __forceinline__ uint32_t smem_u32(const void* p) {
    return (uint32_t)__cvta_generic_to_shared(p);
}
__device__ __forceinline__ void mma_tf32(float* c, const uint32_t* a, const uint32_t* b) {
    asm volatile(
        "mma.sync.aligned.m16n8k8.row.col.f32.tf32.tf32.f32 "
        "{%0,%1,%2,%3}, {%4,%5,%6,%7}, {%8,%9}, {%0,%1,%2,%3};"
        : "+f"(c[0]), "+f"(c[1]), "+f"(c[2]), "+f"(c[3])
        : "r"(a[0]), "r"(a[1]), "r"(a[2]), "r"(a[3]), "r"(b[0]), "r"(b[1]));
}
__device__ __forceinline__ void mma_f16(float* c, const uint32_t* a, const uint32_t* b) {
    asm volatile(
        "mma.sync.aligned.m16n8k16.row.col.f32.f16.f16.f32 "
        "{%0,%1,%2,%3}, {%4,%5,%6,%7}, {%8,%9}, {%0,%1,%2,%3};"
        : "+f"(c[0]), "+f"(c[1]), "+f"(c[2]), "+f"(c[3])
        : "r"(a[0]), "r"(a[1]), "r"(a[2]), "r"(a[3]), "r"(b[0]), "r"(b[1]));
}
__device__ __forceinline__ void row_stats128(float v, float& mu, float& var) {
    float s = v, q = v * v;
    #pragma unroll
    for (int o = 16; o; o >>= 1) {
        s += __shfl_down_sync(0xffffffffu, s, o);
        q += __shfl_down_sync(0xffffffffu, q, o);
    }
    __shared__ float ss[4], sq[4];
    int w = threadIdx.x >> 5;
    if ((threadIdx.x & 31) == 0) { ss[w] = s; sq[w] = q; }
    __syncthreads();
    s = ss[0] + ss[1] + ss[2] + ss[3];
    q = sq[0] + sq[1] + sq[2] + sq[3];
    __syncthreads();
    mu  = s * (1.0f / DMM);
    var = q * (1.0f / DMM) - mu * mu;
}

// ---------------- weight conversion ----------------
__global__ void __launch_bounds__(256) cvt_weights_kernel(
    const float* __restrict__ opw, const float* __restrict__ xpw,
    const float* __restrict__ ipw)
{
    int idx = blockIdx.x * 256 + threadIdx.x;
    const int n_op = 2 * DMM * DII / 2;
    const int n_xp = 2 * 40 * DII / 2;
    const int n_ip = 2 * 2 * DII * DMM / 2;
    if (idx < n_op) {
        float2 v = *(const float2*)(opw + idx * 2);
        ((__half2*)g_opwh)[idx] = __floats2half2_rn(v.x, v.y);
    } else if (idx < n_op + n_xp) {
        int j = idx - n_op;
        float2 v = *(const float2*)(xpw + j * 2);
        ((__half2*)g_xpwh)[j] = __floats2half2_rn(v.x, v.y);
    } else if (idx < n_op + n_xp + n_ip) {
        int j = idx - n_op - n_xp;
        float2 v = *(const float2*)(ipw + j * 2);
        ((__half2*)g_ipwh)[j] = __floats2half2_rn(v.x, v.y);
    }
}

// ---------------- tensorized input projection ----------------
__global__ void __launch_bounds__(256) input_proj_mma(
    const float* __restrict__ x, const float* __restrict__ w, const float* __restrict__ bias)
{
    extern __shared__ float sm[];
    float* As = sm;
    float* Bs = sm + 64 * 68;
    int n = blockIdx.x, t0 = blockIdx.y * 64;
    int tid = threadIdx.x;

    #pragma unroll
    for (int p = 0; p < 4; p++) {
        int f = p * 16 + (tid >> 4), t4 = (tid & 15) * 4;
        float4 v = *(const float4*)(x + ((size_t)(n * FF + f)) * TT + t0 + t4);
        As[(t4 + 0) * 68 + f] = v.x;
        As[(t4 + 1) * 68 + f] = v.y;
        As[(t4 + 2) * 68 + f] = v.z;
        As[(t4 + 3) * 68 + f] = v.w;
    }
    #pragma unroll
    for (int i = 0; i < 8; i++) {
        int idx = tid + i * 256;
        int row = idx >> 4, c4 = (idx & 15) << 2;
        *(float4*)&Bs[row * 68 + c4] = *(const float4*)(w + row * 64 + c4);
    }
    __syncthreads();

    int warp = tid >> 5, lane = tid & 31;
    int gid = lane >> 2, tig = lane & 3;
    int m0 = (warp & 1) * 32, n0 = (warp >> 1) * 32;

    float acc[2][4][4];
    #pragma unroll
    for (int i = 0; i < 2; i++)
        #pragma unroll
        for (int j = 0; j < 4; j++)
            #pragma unroll
            for (int k = 0; k < 4; k++) acc[i][j][k] = 0.f;

    #pragma unroll
    for (int kb = 0; kb < 64; kb += 8) {
        uint32_t afr[2][4], bfr[4][2];
        #pragma unroll
        for (int mt = 0; mt < 2; mt++) {
            int r = m0 + mt * 16 + gid;
            afr[mt][0] = __float_as_uint(As[r * 68 + kb + tig]);
            afr[mt][1] = __float_as_uint(As[(r + 8) * 68 + kb + tig]);
            afr[mt][2] = __float_as_uint(As[r * 68 + kb + tig + 4]);
            afr[mt][3] = __float_as_uint(As[(r + 8) * 68 + kb + tig + 4]);
        }
        #pragma unroll
        for (int nt = 0; nt < 4; nt++) {
            int cn = n0 + nt * 8 + gid;
            bfr[nt][0] = __float_as_uint(Bs[cn * 68 + kb + tig]);
            bfr[nt][1] = __float_as_uint(Bs[cn * 68 + kb + tig + 4]);
        }
        #pragma unroll
        for (int mt = 0; mt < 2; mt++)
            #pragma unroll
            for (int nt = 0; nt < 4; nt++)
                mma_tf32(acc[mt][nt], afr[mt], bfr[nt]);
    }

    __half2* hh = (__half2*)g_hh;
    #pragma unroll
    for (int mt = 0; mt < 2; mt++) {
        int r = n * TT + t0 + m0 + mt * 16 + gid;
        #pragma unroll
        for (int nt = 0; nt < 4; nt++) {
            int cn = n0 + nt * 8 + tig * 2;
            float2 bv = *(const float2*)(bias + cn);
            float v0 = acc[mt][nt][0] + bv.x, v1 = acc[mt][nt][1] + bv.y;
            float v2 = acc[mt][nt][2] + bv.x, v3 = acc[mt][nt][3] + bv.y;
            *(float2*)&g_h[(size_t)r * DMM + cn]       = make_float2(v0, v1);
            *(float2*)&g_h[(size_t)(r + 8) * DMM + cn] = make_float2(v2, v3);
            hh[((size_t)r * DMM + cn) >> 1]       = __floats2half2_rn(v0, v1);
            hh[((size_t)(r + 8) * DMM + cn) >> 1] = __floats2half2_rn(v2, v3);
        }
    }
}

// ---------------- in_proj fp16-HMMA GEMM ----------------
__global__ void __launch_bounds__(256) inproj_kernel(
    const __half* __restrict__ Bw)
{
    const int BK = 16, K = DMM;
    __shared__ __half Ash[2][128][BK + 8];
    __shared__ __half Bsh[2][64][BK + 8];

    int tid  = threadIdx.x;
    int bm   = blockIdx.x * 128, bn = blockIdx.y * 64;
    int warp = tid >> 5, lane = tid & 31;
    int gid  = lane >> 2, tig = lane & 3;
    int m0   = (warp & 3) * 32;
    int n0   = (warp >> 2) * 32;

    float acc[2][4][4];
    #pragma unroll
    for (int i = 0; i < 2; i++)
        #pragma unroll
        for (int j = 0; j < 4; j++)
            #pragma unroll
            for (int k = 0; k < 4; k++) acc[i][j][k] = 0.f;

    int arow = tid >> 1, ahq = (tid & 1) * 8;
    const __half* aptr = g_hh + (size_t)(bm + arow) * K + ahq;
    const __half* bptr = Bw + (size_t)(bn + arow) * K + ahq;
    const int nk = K / BK;

    {
        uint32_t da = smem_u32(&Ash[0][arow][ahq]);
        asm volatile("cp.async.cg.shared.global [%0], [%1], 16;" :: "r"(da), "l"(aptr));
        if (tid < 128) {
            uint32_t db = smem_u32(&Bsh[0][arow][ahq]);
            asm volatile("cp.async.cg.shared.global [%0], [%1], 16;" :: "r"(db), "l"(bptr));
        }
        asm volatile("cp.async.commit_group;");
    }

    for (int i = 0; i < nk; i++) {
        int buf = i & 1;
        asm volatile("cp.async.wait_group 0;");
        __syncthreads();
        if (i + 1 < nk) {
            int k0 = (i + 1) * BK;
            uint32_t da = smem_u32(&Ash[buf ^ 1][arow][ahq]);
            asm volatile("cp.async.cg.shared.global [%0], [%1], 16;" :: "r"(da), "l"(aptr + k0));
            if (tid < 128) {
                uint32_t db = smem_u32(&Bsh[buf ^ 1][arow][ahq]);
                asm volatile("cp.async.cg.shared.global [%0], [%1], 16;" :: "r"(db), "l"(bptr + k0));
            }
            asm volatile("cp.async.commit_group;");
        }
        uint32_t afr[2][4], bfr[4][2];
        #pragma unroll
        for (int mt = 0; mt < 2; mt++) {
            int r = m0 + mt * 16 + gid;
            afr[mt][0] = *(const uint32_t*)&Ash[buf][r    ][tig * 2];
            afr[mt][1] = *(const uint32_t*)&Ash[buf][r + 8][tig * 2];
            afr[mt][2] = *(const uint32_t*)&Ash[buf][r    ][tig * 2 + 8];
            afr[mt][3] = *(const uint32_t*)&Ash[buf][r + 8][tig * 2 + 8];
        }
        #pragma unroll
        for (int nt = 0; nt < 4; nt++) {
            int cn = n0 + nt * 8 + gid;
            bfr[nt][0] = *(const uint32_t*)&Bsh[buf][cn][tig * 2];
            bfr[nt][1] = *(const uint32_t*)&Bsh[buf][cn][tig * 2 + 8];
        }
        #pragma unroll
        for (int mt = 0; mt < 2; mt++)
            #pragma unroll
            for (int nt = 0; nt < 4; nt++)
                mma_f16(acc[mt][nt], afr[mt], bfr[nt]);
    }

    if (bn < DII) {
        __half2* dst = (__half2*)g_xih;
        #pragma unroll
        for (int mt = 0; mt < 2; mt++) {
            int r = bm + m0 + mt * 16 + gid;
            #pragma unroll
            for (int nt = 0; nt < 4; nt++) {
                int cn = bn + n0 + nt * 8 + tig * 2;
                dst[((size_t)r * DII + cn) >> 1] =
                    __floats2half2_rn(acc[mt][nt][0], acc[mt][nt][1]);
                dst[((size_t)(r + 8) * DII + cn) >> 1] =
                    __floats2half2_rn(acc[mt][nt][2], acc[mt][nt][3]);
            }
        }
    } else {
        #pragma unroll
        for (int mt = 0; mt < 2; mt++) {
            int r = bm + m0 + mt * 16 + gid;
            #pragma unroll
            for (int nt = 0; nt < 4; nt++) {
                int cn = (bn - DII) + n0 + nt * 8 + tig * 2;
                float s0 = acc[mt][nt][0], s1 = acc[mt][nt][1];
                float s2 = acc[mt][nt][2], s3 = acc[mt][nt][3];
                s0 = s0 / (1.f + __expf(-s0));
                s1 = s1 / (1.f + __expf(-s1));
                s2 = s2 / (1.f + __expf(-s2));
                s3 = s3 / (1.f + __expf(-s3));
                g_szh[(size_t)r * 128 + (cn >> 1)]       = __floats2half2_rn(s0, s1);
                g_szh[(size_t)(r + 8) * 128 + (cn >> 1)] = __floats2half2_rn(s2, s3);
            }
        }
    }
}

// ---- fused conv(smem,fp16)+silu -> fp16-HMMA x_proj GEMM -> coef; 256 thr, 32-t tile ----
#define USTR 264
__global__ void __launch_bounds__(256) convxproj_kernel(
    const float* __restrict__ cw, const float* __restrict__ cb,
    const float* __restrict__ dtw, const float* __restrict__ dtb, const float* __restrict__ Dv,
    const __half* __restrict__ xpwh)
{
    extern __shared__ char smc[];
    __half* us_h  = (__half*)smc;
    __half* Bsm_h = (__half*)(smc + CXT * USTR * 2);
    float*  xds   = (float*)(smc + CXT * USTR * 2);
    __half* halo  = (__half*)(smc + CXT * USTR * 2 + 40 * USTR * 2);
    int tid = threadIdx.x;
    int n = blockIdx.x >> 3, t0 = (blockIdx.x & 7) * CXT;
    int R0 = n * TT + t0;

    #pragma unroll
    for (int i = 0; i < 5; i++) {
        int idx = tid + i * 256;
        int row = idx >> 5, c8 = (idx & 31) << 3;
        uint32_t dst = smem_u32(&Bsm_h[row * USTR + c8]);
        asm volatile("cp.async.cg.shared.global [%0], [%1], 16;" ::
                     "r"(dst), "l"(xpwh + (size_t)row * 256 + c8));
    }
    {
        const __half* src = g_xih + (size_t)R0 * DII;
        #pragma unroll
        for (int i = 0; i < 4; i++) {
            int idx = tid + i * 256;
            int row = idx >> 5, c8 = (idx & 31) << 3;
            uint32_t dst = smem_u32(&us_h[row * USTR + c8]);
            asm volatile("cp.async.cg.shared.global [%0], [%1], 16;"
                         :: "r"(dst), "l"(src + (size_t)row * DII + c8));
        }
    }
    if (t0 >= 3) {
        if (tid < 96) {
            int row = tid >> 5, c8 = (tid & 31) << 3;
            uint32_t dst = smem_u32(&halo[row * 256 + c8]);
            asm volatile("cp.async.cg.shared.global [%0], [%1], 16;"
                         :: "r"(dst), "l"(g_xih + (size_t)(R0 - 3 + row) * DII + c8));
        }
    } else {
        if (tid < 96) *(float4*)&halo[tid * 8] = make_float4(0.f, 0.f, 0.f, 0.f);
    }
    asm volatile("cp.async.commit_group;");
    asm volatile("cp.async.wait_group 0;");
    __syncthreads();

    {
        int d = tid;
        float w0 = cw[d * 4], w1 = cw[d * 4 + 1], w2 = cw[d * 4 + 2], w3 = cw[d * 4 + 3];
        float bias = cb[d];
        float x0 = __half2float(halo[d]);
        float x1 = __half2float(halo[256 + d]);
        float x2 = __half2float(halo[512 + d]);
        #pragma unroll 4
        for (int tt = 0; tt < CXT; tt += 4) {
            float a0 = __half2float(us_h[(tt + 0) * USTR + d]);
            float a1 = __half2float(us_h[(tt + 1) * USTR + d]);
            float a2 = __half2float(us_h[(tt + 2) * USTR + d]);
            float a3 = __half2float(us_h[(tt + 3) * USTR + d]);
            float s;
            s = w0 * x0 + w1 * x1 + w2 * x2 + w3 * a0 + bias;
            us_h[(tt + 0) * USTR + d] = __float2half_rn(s / (1.f + __expf(-s)));
            s = w0 * x1 + w1 * x2 + w2 * a0 + w3 * a1 + bias;
            us_h[(tt + 1) * USTR + d] = __float2half_rn(s / (1.f + __expf(-s)));
            s = w0 * x2 + w1 * a0 + w2 * a1 + w3 * a2 + bias;
            us_h[(tt + 2) * USTR + d] = __float2half_rn(s / (1.f + __expf(-s)));
            s = w0 * a0 + w1 * a1 + w2 * a2 + w3 * a3 + bias;
            us_h[(tt + 3) * USTR + d] = __float2half_rn(s / (1.f + __expf(-s)));
            x0 = a1; x1 = a2; x2 = a3;
        }
    }
    __syncthreads();

    int warp = tid >> 5, lane = tid & 31;
    int gid = lane >> 2, tig = lane & 3;
    int m0 = (warp & 1) * 16;
    int wg = warp >> 1;
    int nt2 = (wg == 0) ? 2 : 1;
    int cn0 = wg * 8, cn1 = 32;

    float acc[2][4];
    #pragma unroll
    for (int j = 0; j < 2; j++)
        #pragma unroll
        for (int k = 0; k < 4; k++) acc[j][k] = 0.f;

    #pragma unroll 4
    for (int kb = 0; kb < 256; kb += 16) {
        uint32_t afr[4], bfr[2][2];
        int r = m0 + gid;
        afr[0] = *(const uint32_t*)&us_h[r * USTR + kb + tig * 2];
        afr[1] = *(const uint32_t*)&us_h[(r + 8) * USTR + kb + tig * 2];
        afr[2] = *(const uint32_t*)&us_h[r * USTR + kb + tig * 2 + 8];
        afr[3] = *(const uint32_t*)&us_h[(r + 8) * USTR + kb + tig * 2 + 8];
        {
            int cn = cn0 + gid;
            bfr[0][0] = *(const uint32_t*)&Bsm_h[cn * USTR + kb + tig * 2];
            bfr[0][1] = *(const uint32_t*)&Bsm_h[cn * USTR + kb + tig * 2 + 8];
        }
        if (nt2 == 2) {
            int cn = cn1 + gid;
            bfr[1][0] = *(const uint32_t*)&Bsm_h[cn * USTR + kb + tig * 2];
            bfr[1][1] = *(const uint32_t*)&Bsm_h[cn * USTR + kb + tig * 2 + 8];
        }
        mma_f16(acc[0], afr, bfr[0]);
        if (nt2 == 2) mma_f16(acc[1], afr, bfr[1]);
    }

    int q  = tid & 63;
    int rh = tid >> 6;
    float wq[4][8];
    #pragma unroll
    for (int j = 0; j < 4; j++) {
        float4 wa = *(const float4*)(dtw + (size_t)(q * 4 + j) * 8);
        float4 wb = *(const float4*)(dtw + (size_t)(q * 4 + j) * 8 + 4);
        wq[j][0] = wa.x; wq[j][1] = wa.y; wq[j][2] = wa.z; wq[j][3] = wa.w;
        wq[j][4] = wb.x; wq[j][5] = wb.y; wq[j][6] = wb.z; wq[j][7] = wb.w;
    }
    float4 dtb4 = *(const float4*)(dtb + q * 4);
    float4 Dv4  = *(const float4*)(Dv + q * 4);
    float dtbs[4] = {dtb4.x, dtb4.y, dtb4.z, dtb4.w};
    float Dvs[4]  = {Dv4.x, Dv4.y, Dv4.z, Dv4.w};

    __syncthreads();

    {
        int r = m0 + gid;
        {
            int cn = cn0 + tig * 2;
            *(float2*)&g_xdbl[(size_t)(R0 + r) * 40 + cn]     = make_float2(acc[0][0], acc[0][1]);
            *(float2*)&g_xdbl[(size_t)(R0 + r + 8) * 40 + cn] = make_float2(acc[0][2], acc[0][3]);
            *(float2*)&xds[r * 44 + cn]       = make_float2(acc[0][0], acc[0][1]);
            *(float2*)&xds[(r + 8) * 44 + cn] = make_float2(acc[0][2], acc[0][3]);
        }
        if (nt2 == 2) {
            int cn = cn1 + tig * 2;
            *(float2*)&g_xdbl[(size_t)(R0 + r) * 40 + cn]     = make_float2(acc[1][0], acc[1][1]);
            *(float2*)&g_xdbl[(size_t)(R0 + r + 8) * 40 + cn] = make_float2(acc[1][2], acc[1][3]);
            *(float2*)&xds[r * 44 + cn]       = make_float2(acc[1][0], acc[1][1]);
            *(float2*)&xds[(r + 8) * 44 + cn] = make_float2(acc[1][2], acc[1][3]);
        }
    }
    __syncthreads();

    for (int i = 0; i < 8; i++) {
        int row = rh * 8 + i;
        float4 da = *(float4*)&xds[row * 44];
        float4 db = *(float4*)&xds[row * 44 + 4];
        __half2 ua = *(__half2*)&us_h[row * USTR + q * 4];
        __half2 ub = *(__half2*)&us_h[row * USTR + q * 4 + 2];
        float2 u01 = __half22float2(ua), u23 = __half22float2(ub);
        __half2 za = g_szh[(size_t)(R0 + row) * 128 + q * 2];
        __half2 zb = g_szh[(size_t)(R0 + row) * 128 + q * 2 + 1];
        float2 s01 = __half22float2(za), s23 = __half22float2(zb);
        float uu[4] = {u01.x, u01.y, u23.x, u23.y};
        float szv[4] = {s01.x, s01.y, s23.x, s23.y};
        #pragma unroll
        for (int j = 0; j < 4; j++) {
            float dtv = dtbs[j]
                + da.x * wq[j][0] + da.y * wq[j][1] + da.z * wq[j][2] + da.w * wq[j][3]
                + db.x * wq[j][4] + db.y * wq[j][5] + db.z * wq[j][6] + db.w * wq[j][7];
            float pp, delta;
            if (dtv > 15.f) { delta = dtv; pp = __expf(-dtv); }
            else {
                float e1 = __expf(dtv);
                pp = 1.f / (1.f + e1);
                delta = -__logf(pp);
            }
            size_t gidx = (size_t)(R0 + row) * DII + q * 4 + j;
            g_coefA[gidx] = make_float2(delta * uu[j], pp);
            g_coefB[gidx] = __floats2half2_rn(szv[j], uu[j] * Dvs[j]);
        }
    }
}

// ------- fused out_proj fp16-HMMA GEMM + residual + LayerNorm -------
__global__ void __launch_bounds__(256) outproj_ln_kernel(
    const __half* __restrict__ Bw,
    const float* __restrict__ nw, const float* __restrict__ nb)
{
    const int BK = 16, K = DII;
    __shared__ __half Ash[2][64][BK + 8];
    __shared__ __half Bsh[2][DMM][BK + 8];
    __shared__ float  Cs[64][DMM + 4];

    int tid  = threadIdx.x;
    int bm   = blockIdx.x * 64;
    int warp = tid >> 5, lane = tid & 31;
    int gid  = lane >> 2, tig = lane & 3;
    int m0   = (warp & 1) * 32;
    int n0   = (warp >> 1) * 32;

    float acc[2][4][4];
    #pragma unroll
    for (int i = 0; i < 2; i++)
        #pragma unroll
        for (int j = 0; j < 4; j++)
            #pragma unroll
            for (int k = 0; k < 4; k++) acc[i][j][k] = 0.f;

    int arow = tid >> 1, ahq = (tid & 1) * 8;
    int brow = tid >> 1, bhq = (tid & 1) * 8;
    const __half* aptr = g_ymh + (size_t)(bm + arow) * K + ahq;
    const __half* bptr = Bw + (size_t)brow * K + bhq;
    const int nk = K / BK;

    {
        if (tid < 128) {
            uint32_t da = smem_u32(&Ash[0][arow][ahq]);
            asm volatile("cp.async.cg.shared.global [%0], [%1], 16;" :: "r"(da), "l"(aptr));
        }
        uint32_t db = smem_u32(&Bsh[0][brow][bhq]);
        asm volatile("cp.async.cg.shared.global [%0], [%1], 16;" :: "r"(db), "l"(bptr));
        asm volatile("cp.async.commit_group;");
    }

    for (int i = 0; i < nk; i++) {
        int buf = i & 1;
        asm volatile("cp.async.wait_group 0;");
        __syncthreads();
        if (i + 1 < nk) {
            int k0 = (i + 1) * BK;
            if (tid < 128) {
                uint32_t da = smem_u32(&Ash[buf ^ 1][arow][ahq]);
                asm volatile("cp.async.cg.shared.global [%0], [%1], 16;" :: "r"(da), "l"(aptr + k0));
            }
            uint32_t db = smem_u32(&Bsh[buf ^ 1][brow][bhq]);
            asm volatile("cp.async.cg.shared.global [%0], [%1], 16;" :: "r"(db), "l"(bptr + k0));
            asm volatile("cp.async.commit_group;");
        }
        uint32_t afr[2][4], bfr[4][2];
        #pragma unroll
        for (int mt = 0; mt < 2; mt++) {
            int r = m0 + mt * 16 + gid;
            afr[mt][0] = *(const uint32_t*)&Ash[buf][r    ][tig * 2];
            afr[mt][1] = *(const uint32_t*)&Ash[buf][r + 8][tig * 2];
            afr[mt][2] = *(const uint32_t*)&Ash[buf][r    ][tig * 2 + 8];
            afr[mt][3] = *(const uint32_t*)&Ash[buf][r + 8][tig * 2 + 8];
        }
        #pragma unroll
        for (int nt = 0; nt < 4; nt++) {
            int cn = n0 + nt * 8 + gid;
            bfr[nt][0] = *(const uint32_t*)&Bsh[buf][cn][tig * 2];
            bfr[nt][1] = *(const uint32_t*)&Bsh[buf][cn][tig * 2 + 8];
        }
        #pragma unroll
        for (int mt = 0; mt < 2; mt++)
            #pragma unroll
            for (int nt = 0; nt < 4; nt++)
                mma_f16(acc[mt][nt], afr[mt], bfr[nt]);
    }

    #pragma unroll
    for (int mt = 0; mt < 2; mt++) {
        int r = m0 + mt * 16 + gid;
        #pragma unroll
        for (int nt = 0; nt < 4; nt++) {
            int cn = n0 + nt * 8 + tig * 2;
            *(float2*)&Cs[r    ][cn] = make_float2(acc[mt][nt][0], acc[mt][nt][1]);
            *(float2*)&Cs[r + 8][cn] = make_float2(acc[mt][nt][2], acc[mt][nt][3]);
        }
    }
    __syncthreads();

    float w0 = nw[lane], w1 = nw[lane + 32], w2 = nw[lane + 64], w3 = nw[lane + 96];
    float b0 = nb[lane], b1 = nb[lane + 32], b2 = nb[lane + 64], b3 = nb[lane + 96];
    for (int rr = warp * 8; rr < warp * 8 + 8; rr++) {
        size_t gr = (size_t)(bm + rr) * DMM;
        float v0 = Cs[rr][lane]      + g_h[gr + lane];
        float v1 = Cs[rr][lane + 32] + g_h[gr + lane + 32];
        float v2 = Cs[rr][lane + 64] + g_h[gr + lane + 64];
        float v3 = Cs[rr][lane + 96] + g_h[gr + lane + 96];
        float s = v0 + v1 + v2 + v3;
        float q = v0 * v0 + v1 * v1 + v2 * v2 + v3 * v3;
        #pragma unroll
        for (int o = 16; o; o >>= 1) {
            s += __shfl_xor_sync(0xffffffffu, s, o);
            q += __shfl_xor_sync(0xffffffffu, q, o);
        }
        float mu = s * (1.0f / DMM);
        float var = q * (1.0f / DMM) - mu * mu;
        float rs = rsqrtf(var + LNEPS);
        float h0 = (v0 - mu) * rs * w0 + b0;
        float h1 = (v1 - mu) * rs * w1 + b1;
        float h2 = (v2 - mu) * rs * w2 + b2;
        float h3 = (v3 - mu) * rs * w3 + b3;
        g_h[gr + lane]      = h0;
        g_h[gr + lane + 32] = h1;
        g_h[gr + lane + 64] = h2;
        g_h[gr + lane + 96] = h3;
        g_hh[gr + lane]      = __float2half_rn(h0);
        g_hh[gr + lane + 32] = __float2half_rn(h1);
        g_hh[gr + lane + 64] = __float2half_rn(h2);
        g_hh[gr + lane + 96] = __float2half_rn(h3);
    }
}

// ---------------- selective scan: 2-way state split, 256 thr, same 128-block grid ------------
__global__ void __launch_bounds__(256) scan_kernel(const float* __restrict__ alog)
{
    extern __shared__ float sm[];
    float2*  scfA = (float2*)sm;                                // [NBUF][CHK][128]
    __half2* sszd = (__half2*)(sm + NBUF * CHK * 128 * 2);      // [NBUF][CHK][128]
    float*   sbc  = (float*)(sszd + NBUF * CHK * 128);          // [NBUF][CHK][32]

    int n = blockIdx.x, tid = threadIdx.x;
    int ch = tid >> 1, sg = tid & 1;        // channel, state-octet
    int d = blockIdx.y * 128 + ch;
    int dbase = blockIdx.y * 128;

    auto load_chunk = [&](int c, int buf) {
        int T0 = c * CHK;
        const float2* srcA = g_coefA + (size_t)(n * TT + T0) * DII + dbase;
        #pragma unroll
        for (int i = 0; i < 4; i++) {
            int idx = tid + i * 256;                 // 1024 f4
            int t = idx >> 6, cc = (idx & 63) * 2;
            uint32_t dst = smem_u32(&scfA[(buf * CHK + t) * 128 + cc]);
            asm volatile("cp.async.cg.shared.global [%0], [%1], 16;"
                :: "r"(dst), "l"(srcA + (size_t)t * DII + cc));
        }
        const __half2* srcB = g_coefB + (size_t)(n * TT + T0) * DII + dbase;
        #pragma unroll
        for (int i = 0; i < 2; i++) {
            int idx = tid + i * 256;                 // 512 f4
            int t = idx >> 5, cc = (idx & 31) * 4;
            uint32_t dst = smem_u32(&sszd[(buf * CHK + t) * 128 + cc]);
            asm volatile("cp.async.cg.shared.global [%0], [%1], 16;"
                :: "r"(dst), "l"(srcB + (size_t)t * DII + cc));
        }
        if (tid < 128) {
            int t = tid >> 3, j = tid & 7;           // 128 f4
            uint32_t dst = smem_u32(&sbc[(buf * CHK + t) * 32 + j * 4]);
            asm volatile("cp.async.cg.shared.global [%0], [%1], 16;"
                :: "r"(dst), "l"(g_xdbl + (size_t)(n * TT + T0 + t) * 40 + 8 + j * 4));
        }
        asm volatile("cp.async.commit_group;");
    };

    load_chunk(0, 0);
    load_chunk(1, 1);

    float A8[8];
    bool fastA = true;
    #pragma unroll
    for (int j = 0; j < 8; j++) {
        int s = sg * 8 + j;
        A8[j] = -__expf(alog[(size_t)d * DSS + s]);
        fastA = fastA && (A8[j] == -(float)(s + 1));
    }
    float h0 = 0.f, h1 = 0.f, h2 = 0.f, h3 = 0.f;
    float h4 = 0.f, h5 = 0.f, h6 = 0.f, h7 = 0.f;

    size_t base_y = (size_t)n * TT * DII + d;

    for (int c = 0; c < NC; c++) {
        int buf = c & (NBUF - 1);
        if (c + 2 < NC) {
            load_chunk(c + 2, (c + 2) & (NBUF - 1));
            asm volatile("cp.async.wait_group 2;");
        } else if (c + 1 < NC) {
            asm volatile("cp.async.wait_group 1;");
        } else {
            asm volatile("cp.async.wait_group 0;");
        }
        __syncthreads();

        #pragma unroll 4
        for (int tt = 0; tt < CHK; tt++) {
            float2 cf = scfA[(buf * CHK + tt) * 128 + ch];
            __half2 sd = sszd[(buf * CHK + tt) * 128 + ch];
            const float4* bc = (const float4*)(sbc + (buf * CHK + tt) * 32);
            float4 Bv0 = bc[sg * 2], Bv1 = bc[sg * 2 + 1];
            float4 Cv0 = bc[4 + sg * 2], Cv1 = bc[4 + sg * 2 + 1];
            float du = cf.x, p = cf.y;
            float e0, e1, e2, e3, e4, e5, e6, e7;
            if (fastA) {
                float p2 = p * p, p3 = p2 * p, p4 = p2 * p2;
                float p5 = p4 * p, p6 = p4 * p2, p7 = p4 * p3, p8 = p4 * p4;
                float base = sg ? p8 : 1.f;
                e0 = base * p;  e1 = base * p2; e2 = base * p3; e3 = base * p4;
                e4 = base * p5; e5 = base * p6; e6 = base * p7; e7 = base * p8;
            } else {
                float delta = -__logf(p);
                e0 = __expf(delta * A8[0]); e1 = __expf(delta * A8[1]);
                e2 = __expf(delta * A8[2]); e3 = __expf(delta * A8[3]);
                e4 = __expf(delta * A8[4]); e5 = __expf(delta * A8[5]);
                e6 = __expf(delta * A8[6]); e7 = __expf(delta * A8[7]);
            }
            h0 = e0 * h0 + du * Bv0.x;
            h1 = e1 * h1 + du * Bv0.y;
            h2 = e2 * h2 + du * Bv0.z;
            h3 = e3 * h3 + du * Bv0.w;
            h4 = e4 * h4 + du * Bv1.x;
            h5 = e5 * h5 + du * Bv1.y;
            h6 = e6 * h6 + du * Bv1.z;
            h7 = e7 * h7 + du * Bv1.w;
            float y0 = h0 * Cv0.x + h2 * Cv0.z;
            float y1 = h1 * Cv0.y + h3 * Cv0.w;
            float y2 = h4 * Cv1.x + h6 * Cv1.z;
            float y3 = h5 * Cv1.y + h7 * Cv1.w;
            float y = (y0 + y1) + (y2 + y3);
            y += __shfl_xor_sync(0xffffffffu, y, 1);
            if (sg == 0) {
                float2 g = __half22float2(sd);      // g.x = sz, g.y = uD
                g_ymh[base_y + (size_t)(c * CHK + tt) * DII] =
                    __float2half_rn((y + g.y) * g.x);
            }
        }
        __syncthreads();
    }
}

// ---------------- final layernorm + mean over T ----------------
__global__ void __launch_bounds__(128) final_partial_kernel(
    const float* __restrict__ w, const float* __restrict__ b)
{
    int n = blockIdx.x, t0 = blockIdx.y * 64, d = threadIdx.x;
    float wd = w[d], bd = b[d], acc = 0.f;
    for (int tt = 0; tt < 64; tt++) {
        float v = g_h[(size_t)(n * TT + t0 + tt) * DMM + d];
        float mu, var;
        row_stats128(v, mu, var);
        acc += (v - mu) * rsqrtf(var + LNEPS) * wd + bd;
    }
    g_part[(size_t)(n * 4 + blockIdx.y) * DMM + d] = acc;
}

__global__ void __launch_bounds__(128) final_combine_kernel(float* __restrict__ out)
{
    int n = blockIdx.x, d = threadIdx.x;
    float s = g_part[(size_t)(n * 4 + 0) * DMM + d]
            + g_part[(size_t)(n * 4 + 1) * DMM + d]
            + g_part[(size_t)(n * 4 + 2) * DMM + d]
            + g_part[(size_t)(n * 4 + 3) * DMM + d];
    out[(size_t)n * DMM + d] = s * (1.0f / TT);
}

// ---------------- launch ----------------
extern "C" void kernel_launch(void* const* d_in, const int* in_sizes, int n_in,
                              void* d_out, int out_size)
{
    (void)in_sizes; (void)n_in; (void)out_size;
    const float* x     = (const float*)d_in[0];
    const float* inp_w = (const float*)d_in[1];
    const float* inp_b = (const float*)d_in[2];
    const float* ipw   = (const float*)d_in[3];
    const float* cw    = (const float*)d_in[4];
    const float* cb    = (const float*)d_in[5];
    const float* xpw   = (const float*)d_in[6];
    const float* dtw   = (const float*)d_in[7];
    const float* dtb   = (const float*)d_in[8];
    const float* alog  = (const float*)d_in[9];
    const float* Dv    = (const float*)d_in[10];
    const float* opw   = (const float*)d_in[11];
    const float* nw    = (const float*)d_in[12];
    const float* nb    = (const float*)d_in[13];
    const float* onw   = (const float*)d_in[14];
    const float* onb   = (const float*)d_in[15];
    float* out = (float*)d_out;

    __half *popwh, *pxpwh, *pipwh;
    cudaGetSymbolAddress((void**)&popwh, g_opwh);
    cudaGetSymbolAddress((void**)&pxpwh, g_xpwh);
    cudaGetSymbolAddress((void**)&pipwh, g_ipwh);

    const int SMEM_IP = (64 * 68 + 128 * 68) * 4;
    const int SMEM_CX = CXT * USTR * 2 + 40 * USTR * 2 + 3 * 256 * 2;
    const int SMEM_SC = NBUF * CHK * 128 * 8 + NBUF * CHK * 128 * 4 + NBUF * CHK * 32 * 4;
    cudaFuncSetAttribute(input_proj_mma,   cudaFuncAttributeMaxDynamicSharedMemorySize, SMEM_IP);
    cudaFuncSetAttribute(convxproj_kernel, cudaFuncAttributeMaxDynamicSharedMemorySize, SMEM_CX);
    cudaFuncSetAttribute(scan_kernel,      cudaFuncAttributeMaxDynamicSharedMemorySize, SMEM_SC);

    const int n_cvt = 2 * DMM * DII / 2 + 2 * 40 * DII / 2 + 2 * 2 * DII * DMM / 2;
    cvt_weights_kernel<<<(n_cvt + 255) / 256, 256>>>(opw, xpw, ipw);
    input_proj_mma<<<dim3(NSEQ, 4), 256, SMEM_IP>>>(x, inp_w, inp_b);

    for (int l = 0; l < 2; l++) {
        inproj_kernel<<<dim3(ROWS / 128, 8), 256>>>(pipwh + (size_t)l * 2 * DII * DMM);
        convxproj_kernel<<<NSEQ * 8, 256, SMEM_CX>>>(
            cw + (size_t)l * DII * 4, cb + (size_t)l * DII,
            dtw + (size_t)l * DII * DTRR, dtb + (size_t)l * DII, Dv + (size_t)l * DII,
            pxpwh + (size_t)l * 40 * DII);
        scan_kernel<<<dim3(NSEQ, 2), 256, SMEM_SC>>>(alog + (size_t)l * DII * DSS);
        outproj_ln_kernel<<<ROWS / 64, 256>>>(
            popwh + (size_t)l * DMM * DII, nw + (size_t)l * DMM, nb + (size_t)l * DMM);
    }

    final_partial_kernel<<<dim3(NSEQ, 4), 128>>>(onw, onb);
    final_combine_kernel<<<NSEQ, 128>>>(out);
}